// round 14
// baseline (speedup 1.0000x reference)
#include <cuda_runtime.h>
#include <cuda.h>
#include <cuda_bf16.h>
#include <cstdint>

#define B   64
#define S   512
#define V   50257
#define E   512
#define H   1024
#define OOV 12
#define OUTW (V + OOV)     // 50269
#define KX  (E + 2*H)      // 2560
#define TH  (3*H)          // 3072
#define MS  (B*S)          // 32768
#define KC  (2*H)          // 2048

#if defined(__CUDA_ARCH_FEAT_SM103_ALL) || defined(__CUDA_ARCH_FEAT_SM100_ALL)
#define HAS_TC 1
#else
#define HAS_TC 0
#endif

// ---------------- scratch ----------------
__device__ float g_prev[B*H];
__device__ float g_gi[B*TH];
__device__ float g_gh[B*TH];
__device__ float g_scoreg[(size_t)B*V];
__device__ float g_scorec[B*S];
__device__ float g_scorec_raw[B*S];
__device__ float g_rowmax[B];
__device__ float g_rowsum[B];
__device__ __nv_bfloat16 g_Wc_hi[H*KC];
__device__ __nv_bfloat16 g_Wc_lo[H*KC];
__device__ __nv_bfloat16 g_x_hi[B*KX],    g_x_lo[B*KX];
__device__ __nv_bfloat16 g_prev_hi[B*H],  g_prev_lo[B*H];
__device__ __nv_bfloat16 g_state_hi[B*H], g_state_lo[B*H];

__device__ __forceinline__ void split_bf16(float x, uint16_t& h, uint16_t& l){
    __nv_bfloat16 bh = __float2bfloat16_rn(x);
    __nv_bfloat16 bl = __float2bfloat16_rn(x - __bfloat162float(bh));
    h = __bfloat16_as_ushort(bh);
    l = __bfloat16_as_ushort(bl);
}

// ---------------- tcgen05 plumbing ----------------
#if HAS_TC
__device__ __forceinline__ uint32_t smem_u32(const void* p){
    uint32_t a;
    asm("{ .reg .u64 t; cvta.to.shared.u64 t, %1; cvt.u32.u64 %0, t; }" : "=r"(a) : "l"(p));
    return a;
}
__device__ __forceinline__ uint32_t elect_one(){
    uint32_t p;
    asm volatile("{ .reg .pred p; elect.sync _|p, 0xFFFFFFFF; selp.b32 %0, 1, 0, p; }" : "=r"(p));
    return p;
}
#define TC_ALLOC(saddr, n)  asm volatile("tcgen05.alloc.cta_group::1.sync.aligned.shared::cta.b32 [%0], %1;" :: "r"((uint32_t)(saddr)), "r"((uint32_t)(n)) : "memory")
#define TC_DEALLOC(t, n)    asm volatile("tcgen05.dealloc.cta_group::1.sync.aligned.b32 %0, %1;" :: "r"(t), "r"((uint32_t)(n)))
#define TC_RELINQ()         asm volatile("tcgen05.relinquish_alloc_permit.cta_group::1.sync.aligned;")
#define TC_COMMIT(mb)       asm volatile("tcgen05.commit.cta_group::1.mbarrier::arrive::one.shared::cluster.b64 [%0];" :: "r"((uint32_t)(mb)) : "memory")
#define TC_FENCE_AFTER()    asm volatile("tcgen05.fence::after_thread_sync;" ::: "memory")
#define TC_FENCE_BEFORE()   asm volatile("tcgen05.fence::before_thread_sync;" ::: "memory")
#define TC_WAIT_LD()        asm volatile("tcgen05.wait::ld.sync.aligned;" ::: "memory")
#define MBAR_INIT(mb, cnt)  asm volatile("mbarrier.init.shared.b64 [%0], %1;" :: "r"((uint32_t)(mb)), "r"((uint32_t)(cnt)) : "memory")
#define MBAR_EXPECT_TX(mb, bytes) asm volatile("mbarrier.arrive.expect_tx.shared.b64 _, [%0], %1;" :: "r"((uint32_t)(mb)), "r"((uint32_t)(bytes)) : "memory")
#define MBAR_ARRIVE(mb)     asm volatile("mbarrier.arrive.shared.b64 _, [%0];" :: "r"((uint32_t)(mb)) : "memory")
#define TMA_LOAD_2D(sa, mp, cx, cy, mb) \
    asm volatile("cp.async.bulk.tensor.2d.shared::cta.global.tile.mbarrier::complete_tx::bytes [%0], [%1, {%2, %3}], [%4];" \
        :: "r"((uint32_t)(sa)), "l"(mp), "r"((int)(cx)), "r"((int)(cy)), "r"((uint32_t)(mb)) : "memory")
#define MBAR_WAIT(mb, ph) do { \
    uint32_t _m = (uint32_t)(mb); uint32_t _p = (uint32_t)(ph); uint32_t _d; \
    asm volatile("{ .reg .pred p; mbarrier.try_wait.parity.acquire.cta.shared::cta.b64 p, [%1], %2; selp.b32 %0, 1, 0, p; }" \
        : "=r"(_d) : "r"(_m), "r"(_p) : "memory"); \
    if (!_d) { \
        asm volatile("{ .reg .pred P1; WL_%=: mbarrier.try_wait.parity.acquire.cta.shared::cta.b64 P1, [%0], %1, 0x989680; @P1 bra.uni WD_%=; bra.uni WL_%=; WD_%=: }" \
            :: "r"(_m), "r"(_p) : "memory"); \
    } } while(0)

static constexpr uint64_t SMEM_DESC_BASE_SW128 =
    (uint64_t(2)  << 61) | (uint64_t(1) << 46) | (uint64_t(64) << 32) | (uint64_t(1) << 16);
#define MK_DESC(a) (SMEM_DESC_BASE_SW128 | ((uint64_t)((a) >> 4) & 0x3FFF))

#define TC_LD_X32(r, t) \
    asm volatile("tcgen05.ld.sync.aligned.32x32b.x32.b32 " \
        "{%0,%1,%2,%3,%4,%5,%6,%7,%8,%9,%10,%11,%12,%13,%14,%15," \
        "%16,%17,%18,%19,%20,%21,%22,%23,%24,%25,%26,%27,%28,%29,%30,%31}, [%32];" \
        : "=r"((r)[0]),"=r"((r)[1]),"=r"((r)[2]),"=r"((r)[3]),"=r"((r)[4]),"=r"((r)[5]),"=r"((r)[6]),"=r"((r)[7]), \
          "=r"((r)[8]),"=r"((r)[9]),"=r"((r)[10]),"=r"((r)[11]),"=r"((r)[12]),"=r"((r)[13]),"=r"((r)[14]),"=r"((r)[15]), \
          "=r"((r)[16]),"=r"((r)[17]),"=r"((r)[18]),"=r"((r)[19]),"=r"((r)[20]),"=r"((r)[21]),"=r"((r)[22]),"=r"((r)[23]), \
          "=r"((r)[24]),"=r"((r)[25]),"=r"((r)[26]),"=r"((r)[27]),"=r"((r)[28]),"=r"((r)[29]),"=r"((r)[30]),"=r"((r)[31]) \
        : "r"(t))

__device__ __forceinline__ void mma_f16_ss(uint32_t d, uint64_t a, uint64_t b, uint32_t idesc, uint32_t en){
    asm volatile("{ .reg .pred p; setp.ne.u32 p, %4, 0;"
        " tcgen05.mma.cta_group::1.kind::f16 [%0], %1, %2, %3, {%5,%5,%5,%5}, p; }"
        :: "r"(d), "l"(a), "l"(b), "r"(idesc), "r"(en), "r"(0u) : "memory");
}
#endif // HAS_TC

// ==== big fused GEMM: cg1, producer/consumer, TMA B, no __syncthreads in loop ====
#define HDR_SC 4096
#define SSTG 98304
#define T_AH 0
#define T_AL 16384
#define T_BH 32768
#define T_BL 65536
#define TOFF(stg, t) (HDR_SC + (uint32_t)(stg)*SSTG + (uint32_t)(t))
#define SMEM_TC (HDR_SC + 2*SSTG)      // 200704 bytes
#define NCHUNK_SC 32
#define SC_THREADS 512
#define MB_FULL(s)  (8  + (s)*8)       // count 16 = 15 producers + 1 expect_tx (+64KB tx)
#define MB_EMPTY(s) (24 + (s)*8)       // count 1 (tcgen05 commit)
#define MB_DONE     40                 // count 1

__global__ void __launch_bounds__(SC_THREADS, 1)
k_tc_sc(const float* __restrict__ A,
        const __grid_constant__ CUtensorMap mapBh,
        const __grid_constant__ CUtensorMap mapBl,
        const float* __restrict__ bias){
#if HAS_TC
    extern __shared__ char smem[];
    uint32_t sb = smem_u32(smem);
    int tid = threadIdx.x, wid = tid >> 5, lid = tid & 31;
    int n0 = blockIdx.x * 256;
    int m0 = blockIdx.y * 128;
    int b  = m0 >> 9;
    float* s_state = (float*)(smem + 64);
    float* s_bias  = (float*)(smem + 64 + 1024);

    if (wid == 0){ TC_ALLOC(sb + 0, 256); TC_RELINQ(); }
    if (tid == 0){
        MBAR_INIT(sb + MB_FULL(0), 16);
        MBAR_INIT(sb + MB_FULL(1), 16);
        MBAR_INIT(sb + MB_EMPTY(0), 1);
        MBAR_INIT(sb + MB_EMPTY(1), 1);
        MBAR_INIT(sb + MB_DONE, 1);
    }
    if (tid < 256){
        int hb = b*TH;
        int hh = n0 + tid;
        float r = 1.f/(1.f + expf(-(g_gi[hb + hh]       + g_gh[hb + hh])));
        float z = 1.f/(1.f + expf(-(g_gi[hb + H + hh]   + g_gh[hb + H + hh])));
        float n = tanhf(g_gi[hb + 2*H + hh] + r*g_gh[hb + 2*H + hh]);
        s_state[tid] = (1.f - z)*n + z*g_prev[b*H + hh];
        s_bias[tid]  = bias[n0 + tid];
    }
    __syncthreads();
    uint32_t tmem;
    asm volatile("ld.shared.b32 %0, [%1];" : "=r"(tmem) : "r"(sb));

    const uint32_t idesc = (1u<<4) | (1u<<7) | (1u<<10) | (32u<<17) | (8u<<24);

    if (wid == 0){
        // ---------------- MMA warp: no loading ----------------
        int phf[2] = {0, 0};
        for (int c = 0; c < NCHUNK_SC; c++){
            int stg = c & 1;
            MBAR_WAIT(sb + MB_FULL(stg), phf[stg]); phf[stg] ^= 1;
            if (elect_one()){
                uint64_t dAh = MK_DESC(sb + TOFF(stg, T_AH));
                uint64_t dAl = MK_DESC(sb + TOFF(stg, T_AL));
                uint64_t dBh = MK_DESC(sb + TOFF(stg, T_BH));
                uint64_t dBl = MK_DESC(sb + TOFF(stg, T_BL));
                #pragma unroll
                for (int ks = 0; ks < 4; ks++){
                    uint64_t o = (uint64_t)(ks*2);
                    mma_f16_ss(tmem, dAh + o, dBh + o, idesc, (c==0 && ks==0) ? 0u : 1u);
                    mma_f16_ss(tmem, dAh + o, dBl + o, idesc, 1u);
                    mma_f16_ss(tmem, dAl + o, dBh + o, idesc, 1u);
                }
                TC_COMMIT(sb + MB_EMPTY(stg));
            }
        }
        if (elect_one()) TC_COMMIT(sb + MB_DONE);
    } else {
        // ---------------- producer warps 1..15 ----------------
        int ptid = tid - 32;          // 0..479
        int phe[2] = {0, 0};
        for (int c = 0; c < NCHUNK_SC; c++){
            int stg = c & 1;
            if (c >= 2){ MBAR_WAIT(sb + MB_EMPTY(stg), phe[stg]); phe[stg] ^= 1; }
            if (wid == 1 && elect_one()){
                int k0 = c * 64;
                MBAR_EXPECT_TX(sb + MB_FULL(stg), 65536);
                TMA_LOAD_2D(sb + TOFF(stg, T_BH), &mapBh, k0, n0, sb + MB_FULL(stg));
                TMA_LOAD_2D(sb + TOFF(stg, T_BL), &mapBl, k0, n0, sb + MB_FULL(stg));
            }
            int k0 = c * 64;
            for (int i = ptid; i < 2048; i += 480){
                int row = i >> 4, g = i & 15;
                float4 a4 = *(const float4*)(A + (size_t)(m0+row)*KC + k0 + g*4);
                uint16_t h0,h1,h2,h3,l0,l1,l2,l3;
                split_bf16(a4.x,h0,l0); split_bf16(a4.y,h1,l1);
                split_bf16(a4.z,h2,l2); split_bf16(a4.w,h3,l3);
                uint2 hv = make_uint2((uint32_t)h0 | ((uint32_t)h1<<16), (uint32_t)h2 | ((uint32_t)h3<<16));
                uint2 lv = make_uint2((uint32_t)l0 | ((uint32_t)l1<<16), (uint32_t)l2 | ((uint32_t)l3<<16));
                uint32_t off = (uint32_t)(row*128 + g*8);
                uint32_t sw  = off ^ ((off >> 3) & 0x70);
                *(uint2*)(smem + TOFF(stg, T_AH) + sw) = hv;
                *(uint2*)(smem + TOFF(stg, T_AL) + sw) = lv;
            }
            asm volatile("fence.proxy.async.shared::cta;" ::: "memory");
            __syncwarp();
            if (elect_one()) MBAR_ARRIVE(sb + MB_FULL(stg));
        }
    }

    // ---------------- all warps: wait done, epilogue ----------------
    MBAR_WAIT(sb + MB_DONE, 0);
    TC_FENCE_AFTER();

    if (wid < 4){
        float acc = 0.f;
        #pragma unroll
        for (int c0 = 0; c0 < 256; c0 += 32){
            uint32_t r[32];
            TC_LD_X32(r, tmem + c0);
            TC_WAIT_LD();
            #pragma unroll
            for (int j = 0; j < 32; j++)
                acc += tanhf(__uint_as_float(r[j]) + s_bias[c0+j]) * s_state[c0+j];
        }
        TC_FENCE_BEFORE();
        atomicAdd(&g_scorec_raw[m0 + wid*32 + lid], acc);
    }
    __syncthreads();
    if (wid == 0) TC_DEALLOC(tmem, 256);
#endif
}

// ============ generic tc GEMM (unchanged) ============
#define HDR_W 1024
#define WSTG 49152
#define W_AH 0
#define W_AL 16384
#define W_BH 32768
#define W_BL 40960
#define WT_OFF(stg, t) (HDR_W + (uint32_t)(stg)*WSTG + (uint32_t)(t))
#define SMEM_TW (HDR_W + 2*WSTG)

__global__ void __launch_bounds__(256, 1) k_tcW(const float* __restrict__ W,
        const __nv_bfloat16* __restrict__ act_hi, const __nv_bfloat16* __restrict__ act_lo,
        float* __restrict__ out, int Nw, int K, int kpc, int ldO,
        const float* __restrict__ obias){
#if HAS_TC
    extern __shared__ char smem[];
    uint32_t sb = smem_u32(smem);
    int tid = threadIdx.x, wid = tid >> 5, lid = tid & 31;
    int m0 = blockIdx.x * 128;
    int k_base = blockIdx.y * kpc * 64;

    if (wid == 0){ TC_ALLOC(sb + 0, 64); TC_RELINQ(); }
    if (tid == 0){ MBAR_INIT(sb + 8, 1); MBAR_INIT(sb + 16, 1); }
    __syncthreads();
    uint32_t tmem;
    asm volatile("ld.shared.b32 %0, [%1];" : "=r"(tmem) : "r"(sb));

    auto load_chunk = [&](int c, int stg){
        int k0 = k_base + c * 64;
        #pragma unroll
        for (int it = 0; it < 8; it++){
            int i = tid + it*256;
            int row = i >> 4, g = i & 15;
            float4 a4 = make_float4(0.f,0.f,0.f,0.f);
            if (m0 + row < Nw) a4 = *(const float4*)(W + (size_t)(m0+row)*K + k0 + g*4);
            uint16_t h0,h1,h2,h3,l0,l1,l2,l3;
            split_bf16(a4.x,h0,l0); split_bf16(a4.y,h1,l1);
            split_bf16(a4.z,h2,l2); split_bf16(a4.w,h3,l3);
            uint2 hv = make_uint2((uint32_t)h0 | ((uint32_t)h1<<16), (uint32_t)h2 | ((uint32_t)h3<<16));
            uint2 lv = make_uint2((uint32_t)l0 | ((uint32_t)l1<<16), (uint32_t)l2 | ((uint32_t)l3<<16));
            uint32_t off = (uint32_t)(row*128 + g*8);
            uint32_t sw  = off ^ ((off >> 3) & 0x70);
            *(uint2*)(smem + WT_OFF(stg, W_AH) + sw) = hv;
            *(uint2*)(smem + WT_OFF(stg, W_AL) + sw) = lv;
        }
        #pragma unroll
        for (int it = 0; it < 2; it++){
            int i = tid + it*256;
            int row = i >> 3, g = i & 7;
            size_t base = ((size_t)row*K + k0) * 2;
            uint4 h4 = *(const uint4*)((const char*)act_hi + base + g*16);
            uint4 l4 = *(const uint4*)((const char*)act_lo + base + g*16);
            uint32_t off = (uint32_t)(row*128 + g*16);
            uint32_t sw  = off ^ ((off >> 3) & 0x70);
            *(uint4*)(smem + WT_OFF(stg, W_BH) + sw) = h4;
            *(uint4*)(smem + WT_OFF(stg, W_BL) + sw) = l4;
        }
    };

    load_chunk(0, 0);
    asm volatile("fence.proxy.async.shared::cta;" ::: "memory");
    __syncthreads();

    const uint32_t idesc = (1u<<4) | (1u<<7) | (1u<<10) | (8u<<17) | (8u<<24);   // N=64, M=128
    int ph[2] = {0, 0};

    for (int c = 0; c < kpc; c++){
        int stg = c & 1;
        if (wid == 0 && elect_one()){
            uint64_t dAh = MK_DESC(sb + WT_OFF(stg, W_AH));
            uint64_t dAl = MK_DESC(sb + WT_OFF(stg, W_AL));
            uint64_t dBh = MK_DESC(sb + WT_OFF(stg, W_BH));
            uint64_t dBl = MK_DESC(sb + WT_OFF(stg, W_BL));
            #pragma unroll
            for (int ks = 0; ks < 4; ks++){
                uint64_t o = (uint64_t)(ks*2);
                mma_f16_ss(tmem, dAh + o, dBh + o, idesc, (c==0 && ks==0) ? 0u : 1u);
                mma_f16_ss(tmem, dAh + o, dBl + o, idesc, 1u);
                mma_f16_ss(tmem, dAl + o, dBh + o, idesc, 1u);
            }
            TC_COMMIT(sb + 8 + stg*8);
        }
        if (c + 1 < kpc){
            int nst = stg ^ 1;
            if (c >= 1){ MBAR_WAIT(sb + 8 + nst*8, ph[nst]); ph[nst] ^= 1; }
            load_chunk(c + 1, nst);
            asm volatile("fence.proxy.async.shared::cta;" ::: "memory");
            __syncthreads();
        }
    }
    MBAR_WAIT(sb + 8 + ((kpc-1)&1)*8, ph[(kpc-1)&1]);
    TC_FENCE_AFTER();

    if (wid < 4){
        uint32_t r0[32], r1[32];
        TC_LD_X32(r0, tmem);
        TC_LD_X32(r1, tmem + 32);
        TC_WAIT_LD();
        TC_FENCE_BEFORE();
        int m = m0 + wid*32 + lid;
        if (m < Nw){
            if (obias){
                float bv = obias[m];
                #pragma unroll
                for (int c = 0; c < 32; c++)
                    out[(size_t)c*ldO + m] = __uint_as_float(r0[c]) + bv;
                #pragma unroll
                for (int c = 0; c < 32; c++)
                    out[(size_t)(c+32)*ldO + m] = __uint_as_float(r1[c]) + bv;
            } else {
                #pragma unroll
                for (int c = 0; c < 32; c++)
                    atomicAdd(out + (size_t)c*ldO + m, __uint_as_float(r0[c]));
                #pragma unroll
                for (int c = 0; c < 32; c++)
                    atomicAdd(out + (size_t)(c+32)*ldO + m, __uint_as_float(r1[c]));
            }
        }
    }
    __syncthreads();
    if (wid == 0) TC_DEALLOC(tmem, 64);
#endif
}

// ---------------- fused prep ----------------
__global__ void k_prep(const int* __restrict__ input_idx, const float* __restrict__ embed,
                       const float* __restrict__ weighted, const float* __restrict__ prev_state,
                       const float* __restrict__ encoded, const float* __restrict__ Ws_w,
                       const float* __restrict__ Ws_b, const float* __restrict__ bi,
                       const float* __restrict__ bh, const float* __restrict__ Wc,
                       const int* __restrict__ order, int has_order){
    int i = blockIdx.x*blockDim.x + threadIdx.x;
    int ord = has_order ? *order : 1;
    {
        int j = i % TH;
        g_gi[i] = bi[j];
        g_gh[i] = bh[j];
    }
    if (i < B*KX){
        int b = i / KX, j = i - b*KX;
        float v;
        if (j < E) v = embed[(size_t)input_idx[b]*E + j];
        else       v = ord ? weighted[b*(2*H) + (j - E)] : 0.f;
        uint16_t h, l; split_bf16(v, h, l);
        g_x_hi[i] = __ushort_as_bfloat16(h);
        g_x_lo[i] = __ushort_as_bfloat16(l);
    }
    if (i < B*H){
        float v;
        if (ord){
            v = prev_state[i];
        } else {
            int b = i >> 10, h = i & (H-1);
            const float* e = encoded + ((size_t)b*S + (S-1))*(2*H);
            const float* w = Ws_w + (size_t)h*(2*H);
            float s = Ws_b[h];
            for (int k = 0; k < 2*H; k++) s = fmaf(e[k], w[k], s);
            v = s;
        }
        g_prev[i] = v;
        uint16_t h16, l16; split_bf16(v, h16, l16);
        g_prev_hi[i] = __ushort_as_bfloat16(h16);
        g_prev_lo[i] = __ushort_as_bfloat16(l16);
    }
    if (i < B*S) g_scorec_raw[i] = 0.f;
    for (int t = i; t < (H*KC)/4; t += B*TH){
        size_t e = (size_t)t*4;
        float4 w = *(const float4*)(Wc + e);
        uint16_t h0,h1,h2,h3,l0,l1,l2,l3;
        split_bf16(w.x,h0,l0); split_bf16(w.y,h1,l1);
        split_bf16(w.z,h2,l2); split_bf16(w.w,h3,l3);
        uint2 hv = make_uint2((uint32_t)h0 | ((uint32_t)h1<<16), (uint32_t)h2 | ((uint32_t)h3<<16));
        uint2 lv = make_uint2((uint32_t)l0 | ((uint32_t)l1<<16), (uint32_t)l2 | ((uint32_t)l3<<16));
        *(uint2*)((char*)g_Wc_hi + e*2) = hv;
        *(uint2*)((char*)g_Wc_lo + e*2) = lv;
    }
}

// ---------------- GRU combine ----------------
__global__ void k_combine(float* __restrict__ out_state){
    int i = blockIdx.x*blockDim.x + threadIdx.x;
    if (i >= B*H) return;
    int b = i >> 10, h = i & (H-1);
    const float* gi = g_gi + b*TH;
    const float* gh = g_gh + b*TH;
    float r = 1.f/(1.f + expf(-(gi[h]        + gh[h])));
    float z = 1.f/(1.f + expf(-(gi[H + h]    + gh[H + h])));
    float n = tanhf(gi[2*H + h] + r*gh[2*H + h]);
    float st = (1.f - z)*n + z*g_prev[i];
    out_state[i] = st;
    uint16_t h16, l16; split_bf16(st, h16, l16);
    g_state_hi[i] = __ushort_as_bfloat16(h16);
    g_state_lo[i] = __ushort_as_bfloat16(l16);
}

// ---------------- finalize score_c ----------------
__global__ void k_scorec_fin(const int* __restrict__ encoded_idx){
    int m = blockIdx.x*blockDim.x + threadIdx.x;
    float v = tanhf(g_scorec_raw[m]);
    if (encoded_idx[m] == 0) v -= 1000.f;
    g_scorec[m] = v;
}

// ---------------- softmax stats / writeout / tail ----------------
__global__ void k_rowstats(){
    int b = blockIdx.x;
    __shared__ float red[256];
    const float* sg = g_scoreg + (size_t)b*V;
    const float* sc = g_scorec + b*S;
    float mx = -1e30f;
    for (int i = threadIdx.x; i < V; i += 256) mx = fmaxf(mx, sg[i]);
    for (int i = threadIdx.x; i < S; i += 256) mx = fmaxf(mx, sc[i]);
    red[threadIdx.x] = mx; __syncthreads();
    for (int st = 128; st; st >>= 1){
        if (threadIdx.x < st) red[threadIdx.x] = fmaxf(red[threadIdx.x], red[threadIdx.x+st]);
        __syncthreads();
    }
    mx = red[0];
    __syncthreads();
    float sm = 0.f;
    for (int i = threadIdx.x; i < V; i += 256) sm += expf(sg[i] - mx);
    for (int i = threadIdx.x; i < S; i += 256) sm += expf(sc[i] - mx);
    red[threadIdx.x] = sm; __syncthreads();
    for (int st = 128; st; st >>= 1){
        if (threadIdx.x < st) red[threadIdx.x] += red[threadIdx.x+st];
        __syncthreads();
    }
    if (threadIdx.x == 0){ g_rowmax[b] = mx; g_rowsum[b] = red[0]; }
}

__global__ void k_writeout(float* __restrict__ out){
    long long i = (long long)blockIdx.x*256 + threadIdx.x;
    if (i >= (long long)B*OUTW) return;
    int b = (int)(i / OUTW);
    int c = (int)(i - (long long)b*OUTW);
    float v;
    if (c < V) v = expf(g_scoreg[(size_t)b*V + c] - g_rowmax[b]) / g_rowsum[b];
    else       v = 1e-4f;
    out[i] = v;
}

__global__ void k_tail(float* __restrict__ out, float* __restrict__ out_w,
                       const int* __restrict__ encoded_idx, const int* __restrict__ input_idx,
                       const float* __restrict__ encoded){
    int b = blockIdx.x;
    __shared__ float pc[S];
    __shared__ float attn[S];
    __shared__ int   icnt[256];
    float mx  = g_rowmax[b];
    float inv = 1.f / g_rowsum[b];
    int target = input_idx[b];
    int c = 0;
    for (int s = threadIdx.x; s < S; s += 256){
        float p = expf(g_scorec[b*S + s] - mx) * inv;
        pc[s] = p;
        if (encoded_idx[b*S + s] == target) c++;
    }
    icnt[threadIdx.x] = c; __syncthreads();
    for (int st = 128; st; st >>= 1){
        if (threadIdx.x < st) icnt[threadIdx.x] += icnt[threadIdx.x+st];
        __syncthreads();
    }
    int ssum = icnt[0];
    float scale = (ssum > 1) ? 1.f/(float)ssum : 1.f;
    for (int s = threadIdx.x; s < S; s += 256){
        int idx = encoded_idx[b*S + s];
        atomicAdd(&out[(size_t)b*OUTW + idx], pc[s]);
        attn[s] = (idx == target) ? pc[s]*scale : 0.f;
    }
    __syncthreads();
    float acc[8] = {0.f,0.f,0.f,0.f,0.f,0.f,0.f,0.f};
    const float* eb = encoded + (size_t)b*S*(2*H);
    for (int s = 0; s < S; s++){
        float a = attn[s];
        if (a != 0.f){
            const float* er = eb + (size_t)s*(2*H);
            #pragma unroll
            for (int j = 0; j < 8; j++)
                acc[j] = fmaf(a, er[threadIdx.x + j*256], acc[j]);
        }
    }
    #pragma unroll
    for (int j = 0; j < 8; j++)
        out_w[b*(2*H) + threadIdx.x + j*256] = acc[j];
}

// ---------------- launch ----------------
typedef CUresult (*tme_fn_t)(CUtensorMap*, CUtensorMapDataType, cuuint32_t, void*,
                             const cuuint64_t*, const cuuint64_t*, const cuuint32_t*,
                             const cuuint32_t*, CUtensorMapInterleave, CUtensorMapSwizzle,
                             CUtensorMapL2promotion, CUtensorMapFloatOOBfill);

extern "C" void kernel_launch(void* const* d_in, const int* in_sizes, int n_in,
                              void* d_out, int out_size){
    const int*   input_idx   = (const int*)  d_in[0];
    const float* encoded     = (const float*)d_in[1];
    const int*   encoded_idx = (const int*)  d_in[2];
    const float* prev_state  = (const float*)d_in[3];
    const float* weighted    = (const float*)d_in[4];
    int off = 0;
    const int* order = nullptr;
    if (n_in >= 17 && in_sizes[5] == 1){ order = (const int*)d_in[5]; off = 1; }
    const float* embed  = (const float*)d_in[5+off];
    const float* gru_wi = (const float*)d_in[6+off];
    const float* gru_wh = (const float*)d_in[7+off];
    const float* gru_bi = (const float*)d_in[8+off];
    const float* gru_bh = (const float*)d_in[9+off];
    const float* Ws_w   = (const float*)d_in[10+off];
    const float* Ws_b   = (const float*)d_in[11+off];
    const float* Wg_w   = (const float*)d_in[12+off];
    const float* Wg_b   = (const float*)d_in[13+off];
    const float* Wc_w   = (const float*)d_in[14+off];
    const float* Wc_b   = (const float*)d_in[15+off];
    int has_order = (order != nullptr);
    if (!order) order = input_idx;

    float* out       = (float*)d_out;
    float* out_state = out + (size_t)B*OUTW;
    float* out_w     = out_state + (size_t)B*H;

    static float *p_gi = nullptr, *p_gh, *p_scoreg;
    static __nv_bfloat16 *p_Bh, *p_Bl, *p_xh, *p_xl, *p_ph, *p_pl, *p_sh, *p_sl;
    static CUtensorMap mapBh, mapBl;
    if (!p_gi){
        cudaGetSymbolAddress((void**)&p_gi,     g_gi);
        cudaGetSymbolAddress((void**)&p_gh,     g_gh);
        cudaGetSymbolAddress((void**)&p_scoreg, g_scoreg);
        cudaGetSymbolAddress((void**)&p_Bh,     g_Wc_hi);
        cudaGetSymbolAddress((void**)&p_Bl,     g_Wc_lo);
        cudaGetSymbolAddress((void**)&p_xh,     g_x_hi);
        cudaGetSymbolAddress((void**)&p_xl,     g_x_lo);
        cudaGetSymbolAddress((void**)&p_ph,     g_prev_hi);
        cudaGetSymbolAddress((void**)&p_pl,     g_prev_lo);
        cudaGetSymbolAddress((void**)&p_sh,     g_state_hi);
        cudaGetSymbolAddress((void**)&p_sl,     g_state_lo);
        cudaFuncSetAttribute(k_tc_sc, cudaFuncAttributeMaxDynamicSharedMemorySize, SMEM_TC);
        cudaFuncSetAttribute(k_tcW,   cudaFuncAttributeMaxDynamicSharedMemorySize, SMEM_TW);

        void* fn = nullptr;
        cudaDriverEntryPointQueryResult qr;
        cudaGetDriverEntryPointByVersion("cuTensorMapEncodeTiled", &fn, 12000,
                                         cudaEnableDefault, &qr);
        tme_fn_t enc = (tme_fn_t)fn;
        cuuint64_t dims[2]    = {(cuuint64_t)KC, (cuuint64_t)H};
        cuuint64_t strides[1] = {(cuuint64_t)KC * 2};
        cuuint32_t box[2]     = {64, 256};
        cuuint32_t es[2]      = {1, 1};
        enc(&mapBh, CU_TENSOR_MAP_DATA_TYPE_BFLOAT16, 2, p_Bh, dims, strides, box, es,
            CU_TENSOR_MAP_INTERLEAVE_NONE, CU_TENSOR_MAP_SWIZZLE_128B,
            CU_TENSOR_MAP_L2_PROMOTION_L2_128B, CU_TENSOR_MAP_FLOAT_OOB_FILL_NONE);
        enc(&mapBl, CU_TENSOR_MAP_DATA_TYPE_BFLOAT16, 2, p_Bl, dims, strides, box, es,
            CU_TENSOR_MAP_INTERLEAVE_NONE, CU_TENSOR_MAP_SWIZZLE_128B,
            CU_TENSOR_MAP_L2_PROMOTION_L2_128B, CU_TENSOR_MAP_FLOAT_OOB_FILL_NONE);
    }

    // launch 0: fused prep (incl Wc conversion)
    k_prep<<<(B*TH)/256, 256>>>(input_idx, embed, weighted, prev_state, encoded,
                                Ws_w, Ws_b, gru_bi, gru_bh, Wc_w, order, has_order);
    // 1, 2: GRU gate GEMMs
    k_tcW<<<dim3(TH/128, 5), 256, SMEM_TW>>>(gru_wi, p_xh, p_xl, p_gi, TH, KX, 8, TH, nullptr);
    k_tcW<<<dim3(TH/128, 4), 256, SMEM_TW>>>(gru_wh, p_ph, p_pl, p_gh, TH, H,  4, TH, nullptr);
    // 3: big fused GEMM (producer/consumer, CTA-local mbarriers) — ncu capture lands here
    k_tc_sc<<<dim3(H/256, MS/128), SC_THREADS, SMEM_TC>>>(encoded, mapBh, mapBl, Wc_b);
    // 4: combine
    k_combine<<<(B*H)/256, 256>>>(out_state);
    // 5: score_g
    k_tcW<<<dim3((V+127)/128, 1), 256, SMEM_TW>>>(Wg_w, p_sh, p_sl, p_scoreg, V, H, H/64, V, Wg_b);

    k_scorec_fin<<<MS/256, 256>>>(encoded_idx);
    k_rowstats<<<B, 256>>>();
    k_writeout<<<((long long)B*OUTW + 255)/256, 256>>>(out);
    k_tail    <<<B, 256>>>(out, out_w, encoded_idx, input_idx, encoded);
}

// round 15
// speedup vs baseline: 1.4595x; 1.4595x over previous
#include <cuda_runtime.h>
#include <cuda.h>
#include <cuda_bf16.h>
#include <cstdint>

#define B   64
#define S   512
#define V   50257
#define E   512
#define H   1024
#define OOV 12
#define OUTW (V + OOV)     // 50269
#define KX  (E + 2*H)      // 2560
#define TH  (3*H)          // 3072
#define MS  (B*S)          // 32768
#define KC  (2*H)          // 2048

#if defined(__CUDA_ARCH_FEAT_SM103_ALL) || defined(__CUDA_ARCH_FEAT_SM100_ALL)
#define HAS_TC 1
#else
#define HAS_TC 0
#endif

// ---------------- scratch ----------------
__device__ float g_prev[B*H];
__device__ float g_gi[B*TH];
__device__ float g_gh[B*TH];
__device__ float g_scoreg[(size_t)B*V];
__device__ float g_scorec[B*S];
__device__ float g_scorec_raw[B*S];
__device__ float g_rowmax[B];
__device__ float g_rowsum[B];
__device__ __nv_bfloat16 g_Wc_hi[H*KC];
__device__ __nv_bfloat16 g_Wc_lo[H*KC];
__device__ __nv_bfloat16 g_x_hi[B*KX],    g_x_lo[B*KX];
__device__ __nv_bfloat16 g_prev_hi[B*H],  g_prev_lo[B*H];
__device__ __nv_bfloat16 g_state_hi[B*H], g_state_lo[B*H];

__device__ __forceinline__ void split_bf16(float x, uint16_t& h, uint16_t& l){
    __nv_bfloat16 bh = __float2bfloat16_rn(x);
    __nv_bfloat16 bl = __float2bfloat16_rn(x - __bfloat162float(bh));
    h = __bfloat16_as_ushort(bh);
    l = __bfloat16_as_ushort(bl);
}

// ---------------- tcgen05 plumbing ----------------
#if HAS_TC
__device__ __forceinline__ uint32_t smem_u32(const void* p){
    uint32_t a;
    asm("{ .reg .u64 t; cvta.to.shared.u64 t, %1; cvt.u32.u64 %0, t; }" : "=r"(a) : "l"(p));
    return a;
}
__device__ __forceinline__ uint32_t elect_one(){
    uint32_t p;
    asm volatile("{ .reg .pred p; elect.sync _|p, 0xFFFFFFFF; selp.b32 %0, 1, 0, p; }" : "=r"(p));
    return p;
}
#define TC_ALLOC(saddr, n)  asm volatile("tcgen05.alloc.cta_group::1.sync.aligned.shared::cta.b32 [%0], %1;" :: "r"((uint32_t)(saddr)), "r"((uint32_t)(n)) : "memory")
#define TC_DEALLOC(t, n)    asm volatile("tcgen05.dealloc.cta_group::1.sync.aligned.b32 %0, %1;" :: "r"(t), "r"((uint32_t)(n)))
#define TC_RELINQ()         asm volatile("tcgen05.relinquish_alloc_permit.cta_group::1.sync.aligned;")
#define TC_COMMIT(mb)       asm volatile("tcgen05.commit.cta_group::1.mbarrier::arrive::one.shared::cluster.b64 [%0];" :: "r"((uint32_t)(mb)) : "memory")
#define TC_FENCE_AFTER()    asm volatile("tcgen05.fence::after_thread_sync;" ::: "memory")
#define TC_FENCE_BEFORE()   asm volatile("tcgen05.fence::before_thread_sync;" ::: "memory")
#define TC_WAIT_LD()        asm volatile("tcgen05.wait::ld.sync.aligned;" ::: "memory")
#define MBAR_INIT(mb, cnt)  asm volatile("mbarrier.init.shared.b64 [%0], %1;" :: "r"((uint32_t)(mb)), "r"((uint32_t)(cnt)) : "memory")
#define MBAR_EXPECT_TX(mb, bytes) asm volatile("mbarrier.arrive.expect_tx.shared.b64 _, [%0], %1;" :: "r"((uint32_t)(mb)), "r"((uint32_t)(bytes)) : "memory")
#define TMA_LOAD_2D(sa, mp, cx, cy, mb) \
    asm volatile("cp.async.bulk.tensor.2d.shared::cta.global.tile.mbarrier::complete_tx::bytes [%0], [%1, {%2, %3}], [%4];" \
        :: "r"((uint32_t)(sa)), "l"(mp), "r"((int)(cx)), "r"((int)(cy)), "r"((uint32_t)(mb)) : "memory")
#define MBAR_WAIT(mb, ph) do { \
    uint32_t _m = (uint32_t)(mb); uint32_t _p = (uint32_t)(ph); uint32_t _d; \
    asm volatile("{ .reg .pred p; mbarrier.try_wait.parity.acquire.cta.shared::cta.b64 p, [%1], %2; selp.b32 %0, 1, 0, p; }" \
        : "=r"(_d) : "r"(_m), "r"(_p) : "memory"); \
    if (!_d) { \
        asm volatile("{ .reg .pred P1; WL_%=: mbarrier.try_wait.parity.acquire.cta.shared::cta.b64 P1, [%0], %1, 0x989680; @P1 bra.uni WD_%=; bra.uni WL_%=; WD_%=: }" \
            :: "r"(_m), "r"(_p) : "memory"); \
    } } while(0)

static constexpr uint64_t SMEM_DESC_BASE_SW128 =
    (uint64_t(2)  << 61) | (uint64_t(1) << 46) | (uint64_t(64) << 32) | (uint64_t(1) << 16);
#define MK_DESC(a) (SMEM_DESC_BASE_SW128 | ((uint64_t)((a) >> 4) & 0x3FFF))

#define TC_LD_X32(r, t) \
    asm volatile("tcgen05.ld.sync.aligned.32x32b.x32.b32 " \
        "{%0,%1,%2,%3,%4,%5,%6,%7,%8,%9,%10,%11,%12,%13,%14,%15," \
        "%16,%17,%18,%19,%20,%21,%22,%23,%24,%25,%26,%27,%28,%29,%30,%31}, [%32];" \
        : "=r"((r)[0]),"=r"((r)[1]),"=r"((r)[2]),"=r"((r)[3]),"=r"((r)[4]),"=r"((r)[5]),"=r"((r)[6]),"=r"((r)[7]), \
          "=r"((r)[8]),"=r"((r)[9]),"=r"((r)[10]),"=r"((r)[11]),"=r"((r)[12]),"=r"((r)[13]),"=r"((r)[14]),"=r"((r)[15]), \
          "=r"((r)[16]),"=r"((r)[17]),"=r"((r)[18]),"=r"((r)[19]),"=r"((r)[20]),"=r"((r)[21]),"=r"((r)[22]),"=r"((r)[23]), \
          "=r"((r)[24]),"=r"((r)[25]),"=r"((r)[26]),"=r"((r)[27]),"=r"((r)[28]),"=r"((r)[29]),"=r"((r)[30]),"=r"((r)[31]) \
        : "r"(t))

__device__ __forceinline__ void mma_f16_ss(uint32_t d, uint64_t a, uint64_t b, uint32_t idesc, uint32_t en){
    asm volatile("{ .reg .pred p; setp.ne.u32 p, %4, 0;"
        " tcgen05.mma.cta_group::1.kind::f16 [%0], %1, %2, %3, {%5,%5,%5,%5}, p; }"
        :: "r"(d), "l"(a), "l"(b), "r"(idesc), "r"(en), "r"(0u) : "memory");
}
#endif // HAS_TC

// ==== big fused GEMM: cg1, lockstep 2-stage, TMA B, register-prefetched A ====
#define HDR_SC 4096
#define SSTG 98304
#define T_AH 0
#define T_AL 16384
#define T_BH 32768
#define T_BL 65536
#define TOFF(stg, t) (HDR_SC + (uint32_t)(stg)*SSTG + (uint32_t)(t))
#define SMEM_TC (HDR_SC + 2*SSTG)      // 200704 bytes
#define NCHUNK_SC 32
#define SC_THREADS 512
#define MB_FULL(s)  (8  + (s)*8)
#define MB_EMPTY(s) (24 + (s)*8)

__global__ void __launch_bounds__(SC_THREADS, 1)
k_tc_sc(const float* __restrict__ A,
        const __grid_constant__ CUtensorMap mapBh,
        const __grid_constant__ CUtensorMap mapBl,
        const float* __restrict__ bias){
#if HAS_TC
    extern __shared__ char smem[];
    uint32_t sb = smem_u32(smem);
    int tid = threadIdx.x, wid = tid >> 5, lid = tid & 31;
    int n0 = blockIdx.x * 256;
    int m0 = blockIdx.y * 128;
    int b  = m0 >> 9;
    float* s_state = (float*)(smem + 64);
    float* s_bias  = (float*)(smem + 64 + 1024);

    if (wid == 0){ TC_ALLOC(sb + 0, 256); TC_RELINQ(); }
    if (tid == 0){
        MBAR_INIT(sb + MB_FULL(0), 1);
        MBAR_INIT(sb + MB_FULL(1), 1);
        MBAR_INIT(sb + MB_EMPTY(0), 1);
        MBAR_INIT(sb + MB_EMPTY(1), 1);
    }
    if (tid < 256){
        int hb = b*TH;
        int hh = n0 + tid;
        float r = 1.f/(1.f + expf(-(g_gi[hb + hh]       + g_gh[hb + hh])));
        float z = 1.f/(1.f + expf(-(g_gi[hb + H + hh]   + g_gh[hb + H + hh])));
        float n = tanhf(g_gi[hb + 2*H + hh] + r*g_gh[hb + 2*H + hh]);
        s_state[tid] = (1.f - z)*n + z*g_prev[b*H + hh];
        s_bias[tid]  = bias[n0 + tid];
    }
    __syncthreads();
    uint32_t tmem;
    asm volatile("ld.shared.b32 %0, [%1];" : "=r"(tmem) : "r"(sb));

    // per-thread A slice coordinates (fixed across chunks): 4 float4 groups
    int rowi[4], gi4[4];
    #pragma unroll
    for (int it = 0; it < 4; it++){
        int i = tid + it*SC_THREADS;
        rowi[it] = i >> 4; gi4[it] = i & 15;
    }

    auto prefetch_A = [&](int c, float4* pf){
        int k0 = c * 64;
        #pragma unroll
        for (int it = 0; it < 4; it++)
            pf[it] = *(const float4*)(A + (size_t)(m0+rowi[it])*KC + k0 + gi4[it]*4);
    };
    auto store_A = [&](int stg, const float4* pf){
        #pragma unroll
        for (int it = 0; it < 4; it++){
            float4 a4 = pf[it];
            uint16_t h0,h1,h2,h3,l0,l1,l2,l3;
            split_bf16(a4.x,h0,l0); split_bf16(a4.y,h1,l1);
            split_bf16(a4.z,h2,l2); split_bf16(a4.w,h3,l3);
            uint2 hv = make_uint2((uint32_t)h0 | ((uint32_t)h1<<16), (uint32_t)h2 | ((uint32_t)h3<<16));
            uint2 lv = make_uint2((uint32_t)l0 | ((uint32_t)l1<<16), (uint32_t)l2 | ((uint32_t)l3<<16));
            uint32_t off = (uint32_t)(rowi[it]*128 + gi4[it]*8);
            uint32_t sw  = off ^ ((off >> 3) & 0x70);
            *(uint2*)(smem + TOFF(stg, T_AH) + sw) = hv;
            *(uint2*)(smem + TOFF(stg, T_AL) + sw) = lv;
        }
    };
    auto issue_B = [&](int c, int stg){
        int k0 = c * 64;
        MBAR_EXPECT_TX(sb + MB_FULL(stg), 65536);
        TMA_LOAD_2D(sb + TOFF(stg, T_BH), &mapBh, k0, n0, sb + MB_FULL(stg));
        TMA_LOAD_2D(sb + TOFF(stg, T_BL), &mapBl, k0, n0, sb + MB_FULL(stg));
    };

    float4 pf[4];
    if (wid == 1 && elect_one()) issue_B(0, 0);
    prefetch_A(0, pf);
    store_A(0, pf);
    asm volatile("fence.proxy.async.shared::cta;" ::: "memory");
    __syncthreads();

    const uint32_t idesc = (1u<<4) | (1u<<7) | (1u<<10) | (32u<<17) | (8u<<24);
    int phf[2] = {0, 0};
    int phe[2] = {0, 0};

    for (int c = 0; c < NCHUNK_SC; c++){
        int stg = c & 1;
        if (wid == 0 && elect_one()){
            MBAR_WAIT(sb + MB_FULL(stg), phf[stg]); phf[stg] ^= 1;   // B (TMA) ready
            uint64_t dAh = MK_DESC(sb + TOFF(stg, T_AH));
            uint64_t dAl = MK_DESC(sb + TOFF(stg, T_AL));
            uint64_t dBh = MK_DESC(sb + TOFF(stg, T_BH));
            uint64_t dBl = MK_DESC(sb + TOFF(stg, T_BL));
            #pragma unroll
            for (int ks = 0; ks < 4; ks++){
                uint64_t o = (uint64_t)(ks*2);
                mma_f16_ss(tmem, dAh + o, dBh + o, idesc, (c==0 && ks==0) ? 0u : 1u);
                mma_f16_ss(tmem, dAh + o, dBl + o, idesc, 1u);
                mma_f16_ss(tmem, dAl + o, dBh + o, idesc, 1u);
            }
            TC_COMMIT(sb + MB_EMPTY(stg));
        }
        if (c + 1 < NCHUNK_SC){
            int nst = stg ^ 1;
            prefetch_A(c + 1, pf);                 // LDG into regs BEFORE the wait
            if (c >= 1){ MBAR_WAIT(sb + MB_EMPTY(nst), phe[nst]); phe[nst] ^= 1; }
            if (wid == 1 && elect_one()) issue_B(c + 1, nst);
            store_A(nst, pf);                      // convert + STS only
            asm volatile("fence.proxy.async.shared::cta;" ::: "memory");
            __syncthreads();
        }
    }
    MBAR_WAIT(sb + MB_EMPTY((NCHUNK_SC-1)&1), phe[(NCHUNK_SC-1)&1]);
    TC_FENCE_AFTER();

    if (wid < 4){
        float acc = 0.f;
        #pragma unroll
        for (int c0 = 0; c0 < 256; c0 += 32){
            uint32_t r[32];
            TC_LD_X32(r, tmem + c0);
            TC_WAIT_LD();
            #pragma unroll
            for (int j = 0; j < 32; j++)
                acc += tanhf(__uint_as_float(r[j]) + s_bias[c0+j]) * s_state[c0+j];
        }
        TC_FENCE_BEFORE();
        atomicAdd(&g_scorec_raw[m0 + wid*32 + lid], acc);
    }
    __syncthreads();
    if (wid == 0) TC_DEALLOC(tmem, 256);
#endif
}

// ============ generic tc GEMM (unchanged) ============
#define HDR_W 1024
#define WSTG 49152
#define W_AH 0
#define W_AL 16384
#define W_BH 32768
#define W_BL 40960
#define WT_OFF(stg, t) (HDR_W + (uint32_t)(stg)*WSTG + (uint32_t)(t))
#define SMEM_TW (HDR_W + 2*WSTG)

__global__ void __launch_bounds__(256, 1) k_tcW(const float* __restrict__ W,
        const __nv_bfloat16* __restrict__ act_hi, const __nv_bfloat16* __restrict__ act_lo,
        float* __restrict__ out, int Nw, int K, int kpc, int ldO,
        const float* __restrict__ obias){
#if HAS_TC
    extern __shared__ char smem[];
    uint32_t sb = smem_u32(smem);
    int tid = threadIdx.x, wid = tid >> 5, lid = tid & 31;
    int m0 = blockIdx.x * 128;
    int k_base = blockIdx.y * kpc * 64;

    if (wid == 0){ TC_ALLOC(sb + 0, 64); TC_RELINQ(); }
    if (tid == 0){ MBAR_INIT(sb + 8, 1); MBAR_INIT(sb + 16, 1); }
    __syncthreads();
    uint32_t tmem;
    asm volatile("ld.shared.b32 %0, [%1];" : "=r"(tmem) : "r"(sb));

    auto load_chunk = [&](int c, int stg){
        int k0 = k_base + c * 64;
        #pragma unroll
        for (int it = 0; it < 8; it++){
            int i = tid + it*256;
            int row = i >> 4, g = i & 15;
            float4 a4 = make_float4(0.f,0.f,0.f,0.f);
            if (m0 + row < Nw) a4 = *(const float4*)(W + (size_t)(m0+row)*K + k0 + g*4);
            uint16_t h0,h1,h2,h3,l0,l1,l2,l3;
            split_bf16(a4.x,h0,l0); split_bf16(a4.y,h1,l1);
            split_bf16(a4.z,h2,l2); split_bf16(a4.w,h3,l3);
            uint2 hv = make_uint2((uint32_t)h0 | ((uint32_t)h1<<16), (uint32_t)h2 | ((uint32_t)h3<<16));
            uint2 lv = make_uint2((uint32_t)l0 | ((uint32_t)l1<<16), (uint32_t)l2 | ((uint32_t)l3<<16));
            uint32_t off = (uint32_t)(row*128 + g*8);
            uint32_t sw  = off ^ ((off >> 3) & 0x70);
            *(uint2*)(smem + WT_OFF(stg, W_AH) + sw) = hv;
            *(uint2*)(smem + WT_OFF(stg, W_AL) + sw) = lv;
        }
        #pragma unroll
        for (int it = 0; it < 2; it++){
            int i = tid + it*256;
            int row = i >> 3, g = i & 7;
            size_t base = ((size_t)row*K + k0) * 2;
            uint4 h4 = *(const uint4*)((const char*)act_hi + base + g*16);
            uint4 l4 = *(const uint4*)((const char*)act_lo + base + g*16);
            uint32_t off = (uint32_t)(row*128 + g*16);
            uint32_t sw  = off ^ ((off >> 3) & 0x70);
            *(uint4*)(smem + WT_OFF(stg, W_BH) + sw) = h4;
            *(uint4*)(smem + WT_OFF(stg, W_BL) + sw) = l4;
        }
    };

    load_chunk(0, 0);
    asm volatile("fence.proxy.async.shared::cta;" ::: "memory");
    __syncthreads();

    const uint32_t idesc = (1u<<4) | (1u<<7) | (1u<<10) | (8u<<17) | (8u<<24);   // N=64, M=128
    int ph[2] = {0, 0};

    for (int c = 0; c < kpc; c++){
        int stg = c & 1;
        if (wid == 0 && elect_one()){
            uint64_t dAh = MK_DESC(sb + WT_OFF(stg, W_AH));
            uint64_t dAl = MK_DESC(sb + WT_OFF(stg, W_AL));
            uint64_t dBh = MK_DESC(sb + WT_OFF(stg, W_BH));
            uint64_t dBl = MK_DESC(sb + WT_OFF(stg, W_BL));
            #pragma unroll
            for (int ks = 0; ks < 4; ks++){
                uint64_t o = (uint64_t)(ks*2);
                mma_f16_ss(tmem, dAh + o, dBh + o, idesc, (c==0 && ks==0) ? 0u : 1u);
                mma_f16_ss(tmem, dAh + o, dBl + o, idesc, 1u);
                mma_f16_ss(tmem, dAl + o, dBh + o, idesc, 1u);
            }
            TC_COMMIT(sb + 8 + stg*8);
        }
        if (c + 1 < kpc){
            int nst = stg ^ 1;
            if (c >= 1){ MBAR_WAIT(sb + 8 + nst*8, ph[nst]); ph[nst] ^= 1; }
            load_chunk(c + 1, nst);
            asm volatile("fence.proxy.async.shared::cta;" ::: "memory");
            __syncthreads();
        }
    }
    MBAR_WAIT(sb + 8 + ((kpc-1)&1)*8, ph[(kpc-1)&1]);
    TC_FENCE_AFTER();

    if (wid < 4){
        uint32_t r0[32], r1[32];
        TC_LD_X32(r0, tmem);
        TC_LD_X32(r1, tmem + 32);
        TC_WAIT_LD();
        TC_FENCE_BEFORE();
        int m = m0 + wid*32 + lid;
        if (m < Nw){
            if (obias){
                float bv = obias[m];
                #pragma unroll
                for (int c = 0; c < 32; c++)
                    out[(size_t)c*ldO + m] = __uint_as_float(r0[c]) + bv;
                #pragma unroll
                for (int c = 0; c < 32; c++)
                    out[(size_t)(c+32)*ldO + m] = __uint_as_float(r1[c]) + bv;
            } else {
                #pragma unroll
                for (int c = 0; c < 32; c++)
                    atomicAdd(out + (size_t)c*ldO + m, __uint_as_float(r0[c]));
                #pragma unroll
                for (int c = 0; c < 32; c++)
                    atomicAdd(out + (size_t)(c+32)*ldO + m, __uint_as_float(r1[c]));
            }
        }
    }
    __syncthreads();
    if (wid == 0) TC_DEALLOC(tmem, 64);
#endif
}

// ---------------- fused prep ----------------
__global__ void k_prep(const int* __restrict__ input_idx, const float* __restrict__ embed,
                       const float* __restrict__ weighted, const float* __restrict__ prev_state,
                       const float* __restrict__ encoded, const float* __restrict__ Ws_w,
                       const float* __restrict__ Ws_b, const float* __restrict__ bi,
                       const float* __restrict__ bh, const float* __restrict__ Wc,
                       const int* __restrict__ order, int has_order){
    int i = blockIdx.x*blockDim.x + threadIdx.x;
    int ord = has_order ? *order : 1;
    {
        int j = i % TH;
        g_gi[i] = bi[j];
        g_gh[i] = bh[j];
    }
    if (i < B*KX){
        int b = i / KX, j = i - b*KX;
        float v;
        if (j < E) v = embed[(size_t)input_idx[b]*E + j];
        else       v = ord ? weighted[b*(2*H) + (j - E)] : 0.f;
        uint16_t h, l; split_bf16(v, h, l);
        g_x_hi[i] = __ushort_as_bfloat16(h);
        g_x_lo[i] = __ushort_as_bfloat16(l);
    }
    if (i < B*H){
        float v;
        if (ord){
            v = prev_state[i];
        } else {
            int b = i >> 10, h = i & (H-1);
            const float* e = encoded + ((size_t)b*S + (S-1))*(2*H);
            const float* w = Ws_w + (size_t)h*(2*H);
            float s = Ws_b[h];
            for (int k = 0; k < 2*H; k++) s = fmaf(e[k], w[k], s);
            v = s;
        }
        g_prev[i] = v;
        uint16_t h16, l16; split_bf16(v, h16, l16);
        g_prev_hi[i] = __ushort_as_bfloat16(h16);
        g_prev_lo[i] = __ushort_as_bfloat16(l16);
    }
    if (i < B*S) g_scorec_raw[i] = 0.f;
    for (int t = i; t < (H*KC)/4; t += B*TH){
        size_t e = (size_t)t*4;
        float4 w = *(const float4*)(Wc + e);
        uint16_t h0,h1,h2,h3,l0,l1,l2,l3;
        split_bf16(w.x,h0,l0); split_bf16(w.y,h1,l1);
        split_bf16(w.z,h2,l2); split_bf16(w.w,h3,l3);
        uint2 hv = make_uint2((uint32_t)h0 | ((uint32_t)h1<<16), (uint32_t)h2 | ((uint32_t)h3<<16));
        uint2 lv = make_uint2((uint32_t)l0 | ((uint32_t)l1<<16), (uint32_t)l2 | ((uint32_t)l3<<16));
        *(uint2*)((char*)g_Wc_hi + e*2) = hv;
        *(uint2*)((char*)g_Wc_lo + e*2) = lv;
    }
}

// ---------------- GRU combine ----------------
__global__ void k_combine(float* __restrict__ out_state){
    int i = blockIdx.x*blockDim.x + threadIdx.x;
    if (i >= B*H) return;
    int b = i >> 10, h = i & (H-1);
    const float* gi = g_gi + b*TH;
    const float* gh = g_gh + b*TH;
    float r = 1.f/(1.f + expf(-(gi[h]        + gh[h])));
    float z = 1.f/(1.f + expf(-(gi[H + h]    + gh[H + h])));
    float n = tanhf(gi[2*H + h] + r*gh[2*H + h]);
    float st = (1.f - z)*n + z*g_prev[i];
    out_state[i] = st;
    uint16_t h16, l16; split_bf16(st, h16, l16);
    g_state_hi[i] = __ushort_as_bfloat16(h16);
    g_state_lo[i] = __ushort_as_bfloat16(l16);
}

// ---------------- finalize score_c ----------------
__global__ void k_scorec_fin(const int* __restrict__ encoded_idx){
    int m = blockIdx.x*blockDim.x + threadIdx.x;
    float v = tanhf(g_scorec_raw[m]);
    if (encoded_idx[m] == 0) v -= 1000.f;
    g_scorec[m] = v;
}

// ---------------- softmax stats / writeout / tail ----------------
__global__ void k_rowstats(){
    int b = blockIdx.x;
    __shared__ float red[256];
    const float* sg = g_scoreg + (size_t)b*V;
    const float* sc = g_scorec + b*S;
    float mx = -1e30f;
    for (int i = threadIdx.x; i < V; i += 256) mx = fmaxf(mx, sg[i]);
    for (int i = threadIdx.x; i < S; i += 256) mx = fmaxf(mx, sc[i]);
    red[threadIdx.x] = mx; __syncthreads();
    for (int st = 128; st; st >>= 1){
        if (threadIdx.x < st) red[threadIdx.x] = fmaxf(red[threadIdx.x], red[threadIdx.x+st]);
        __syncthreads();
    }
    mx = red[0];
    __syncthreads();
    float sm = 0.f;
    for (int i = threadIdx.x; i < V; i += 256) sm += expf(sg[i] - mx);
    for (int i = threadIdx.x; i < S; i += 256) sm += expf(sc[i] - mx);
    red[threadIdx.x] = sm; __syncthreads();
    for (int st = 128; st; st >>= 1){
        if (threadIdx.x < st) red[threadIdx.x] += red[threadIdx.x+st];
        __syncthreads();
    }
    if (threadIdx.x == 0){ g_rowmax[b] = mx; g_rowsum[b] = red[0]; }
}

__global__ void k_writeout(float* __restrict__ out){
    long long i = (long long)blockIdx.x*256 + threadIdx.x;
    if (i >= (long long)B*OUTW) return;
    int b = (int)(i / OUTW);
    int c = (int)(i - (long long)b*OUTW);
    float v;
    if (c < V) v = expf(g_scoreg[(size_t)b*V + c] - g_rowmax[b]) / g_rowsum[b];
    else       v = 1e-4f;
    out[i] = v;
}

__global__ void k_tail(float* __restrict__ out, float* __restrict__ out_w,
                       const int* __restrict__ encoded_idx, const int* __restrict__ input_idx,
                       const float* __restrict__ encoded){
    int b = blockIdx.x;
    __shared__ float pc[S];
    __shared__ float attn[S];
    __shared__ int   icnt[256];
    float mx  = g_rowmax[b];
    float inv = 1.f / g_rowsum[b];
    int target = input_idx[b];
    int c = 0;
    for (int s = threadIdx.x; s < S; s += 256){
        float p = expf(g_scorec[b*S + s] - mx) * inv;
        pc[s] = p;
        if (encoded_idx[b*S + s] == target) c++;
    }
    icnt[threadIdx.x] = c; __syncthreads();
    for (int st = 128; st; st >>= 1){
        if (threadIdx.x < st) icnt[threadIdx.x] += icnt[threadIdx.x+st];
        __syncthreads();
    }
    int ssum = icnt[0];
    float scale = (ssum > 1) ? 1.f/(float)ssum : 1.f;
    for (int s = threadIdx.x; s < S; s += 256){
        int idx = encoded_idx[b*S + s];
        atomicAdd(&out[(size_t)b*OUTW + idx], pc[s]);
        attn[s] = (idx == target) ? pc[s]*scale : 0.f;
    }
    __syncthreads();
    float acc[8] = {0.f,0.f,0.f,0.f,0.f,0.f,0.f,0.f};
    const float* eb = encoded + (size_t)b*S*(2*H);
    for (int s = 0; s < S; s++){
        float a = attn[s];
        if (a != 0.f){
            const float* er = eb + (size_t)s*(2*H);
            #pragma unroll
            for (int j = 0; j < 8; j++)
                acc[j] = fmaf(a, er[threadIdx.x + j*256], acc[j]);
        }
    }
    #pragma unroll
    for (int j = 0; j < 8; j++)
        out_w[b*(2*H) + threadIdx.x + j*256] = acc[j];
}

// ---------------- launch ----------------
typedef CUresult (*tme_fn_t)(CUtensorMap*, CUtensorMapDataType, cuuint32_t, void*,
                             const cuuint64_t*, const cuuint64_t*, const cuuint32_t*,
                             const cuuint32_t*, CUtensorMapInterleave, CUtensorMapSwizzle,
                             CUtensorMapL2promotion, CUtensorMapFloatOOBfill);

extern "C" void kernel_launch(void* const* d_in, const int* in_sizes, int n_in,
                              void* d_out, int out_size){
    const int*   input_idx   = (const int*)  d_in[0];
    const float* encoded     = (const float*)d_in[1];
    const int*   encoded_idx = (const int*)  d_in[2];
    const float* prev_state  = (const float*)d_in[3];
    const float* weighted    = (const float*)d_in[4];
    int off = 0;
    const int* order = nullptr;
    if (n_in >= 17 && in_sizes[5] == 1){ order = (const int*)d_in[5]; off = 1; }
    const float* embed  = (const float*)d_in[5+off];
    const float* gru_wi = (const float*)d_in[6+off];
    const float* gru_wh = (const float*)d_in[7+off];
    const float* gru_bi = (const float*)d_in[8+off];
    const float* gru_bh = (const float*)d_in[9+off];
    const float* Ws_w   = (const float*)d_in[10+off];
    const float* Ws_b   = (const float*)d_in[11+off];
    const float* Wg_w   = (const float*)d_in[12+off];
    const float* Wg_b   = (const float*)d_in[13+off];
    const float* Wc_w   = (const float*)d_in[14+off];
    const float* Wc_b   = (const float*)d_in[15+off];
    int has_order = (order != nullptr);
    if (!order) order = input_idx;

    float* out       = (float*)d_out;
    float* out_state = out + (size_t)B*OUTW;
    float* out_w     = out_state + (size_t)B*H;

    static float *p_gi = nullptr, *p_gh, *p_scoreg;
    static __nv_bfloat16 *p_Bh, *p_Bl, *p_xh, *p_xl, *p_ph, *p_pl, *p_sh, *p_sl;
    static CUtensorMap mapBh, mapBl;
    if (!p_gi){
        cudaGetSymbolAddress((void**)&p_gi,     g_gi);
        cudaGetSymbolAddress((void**)&p_gh,     g_gh);
        cudaGetSymbolAddress((void**)&p_scoreg, g_scoreg);
        cudaGetSymbolAddress((void**)&p_Bh,     g_Wc_hi);
        cudaGetSymbolAddress((void**)&p_Bl,     g_Wc_lo);
        cudaGetSymbolAddress((void**)&p_xh,     g_x_hi);
        cudaGetSymbolAddress((void**)&p_xl,     g_x_lo);
        cudaGetSymbolAddress((void**)&p_ph,     g_prev_hi);
        cudaGetSymbolAddress((void**)&p_pl,     g_prev_lo);
        cudaGetSymbolAddress((void**)&p_sh,     g_state_hi);
        cudaGetSymbolAddress((void**)&p_sl,     g_state_lo);
        cudaFuncSetAttribute(k_tc_sc, cudaFuncAttributeMaxDynamicSharedMemorySize, SMEM_TC);
        cudaFuncSetAttribute(k_tcW,   cudaFuncAttributeMaxDynamicSharedMemorySize, SMEM_TW);

        void* fn = nullptr;
        cudaDriverEntryPointQueryResult qr;
        cudaGetDriverEntryPointByVersion("cuTensorMapEncodeTiled", &fn, 12000,
                                         cudaEnableDefault, &qr);
        tme_fn_t enc = (tme_fn_t)fn;
        cuuint64_t dims[2]    = {(cuuint64_t)KC, (cuuint64_t)H};
        cuuint64_t strides[1] = {(cuuint64_t)KC * 2};
        cuuint32_t box[2]     = {64, 256};
        cuuint32_t es[2]      = {1, 1};
        enc(&mapBh, CU_TENSOR_MAP_DATA_TYPE_BFLOAT16, 2, p_Bh, dims, strides, box, es,
            CU_TENSOR_MAP_INTERLEAVE_NONE, CU_TENSOR_MAP_SWIZZLE_128B,
            CU_TENSOR_MAP_L2_PROMOTION_L2_128B, CU_TENSOR_MAP_FLOAT_OOB_FILL_NONE);
        enc(&mapBl, CU_TENSOR_MAP_DATA_TYPE_BFLOAT16, 2, p_Bl, dims, strides, box, es,
            CU_TENSOR_MAP_INTERLEAVE_NONE, CU_TENSOR_MAP_SWIZZLE_128B,
            CU_TENSOR_MAP_L2_PROMOTION_L2_128B, CU_TENSOR_MAP_FLOAT_OOB_FILL_NONE);
    }

    // launch 0: fused prep (incl Wc conversion)
    k_prep<<<(B*TH)/256, 256>>>(input_idx, embed, weighted, prev_state, encoded,
                                Ws_w, Ws_b, gru_bi, gru_bh, Wc_w, order, has_order);
    // 1, 2: GRU gate GEMMs
    k_tcW<<<dim3(TH/128, 5), 256, SMEM_TW>>>(gru_wi, p_xh, p_xl, p_gi, TH, KX, 8, TH, nullptr);
    k_tcW<<<dim3(TH/128, 4), 256, SMEM_TW>>>(gru_wh, p_ph, p_pl, p_gh, TH, H,  4, TH, nullptr);
    // 3: big fused GEMM (lockstep + A register prefetch) — ncu capture lands here
    k_tc_sc<<<dim3(H/256, MS/128), SC_THREADS, SMEM_TC>>>(encoded, mapBh, mapBl, Wc_b);
    // 4: combine
    k_combine<<<(B*H)/256, 256>>>(out_state);
    // 5: score_g
    k_tcW<<<dim3((V+127)/128, 1), 256, SMEM_TW>>>(Wg_w, p_sh, p_sl, p_scoreg, V, H, H/64, V, Wg_b);

    k_scorec_fin<<<MS/256, 256>>>(encoded_idx);
    k_rowstats<<<B, 256>>>();
    k_writeout<<<((long long)B*OUTW + 255)/256, 256>>>(out);
    k_tail    <<<B, 256>>>(out, out_w, encoded_idx, input_idx, encoded);
}

// round 16
// speedup vs baseline: 2.0209x; 1.3847x over previous
#include <cuda_runtime.h>
#include <cuda.h>
#include <cuda_bf16.h>
#include <cstdint>

#define B   64
#define S   512
#define V   50257
#define E   512
#define H   1024
#define OOV 12
#define OUTW (V + OOV)     // 50269
#define KX  (E + 2*H)      // 2560
#define TH  (3*H)          // 3072
#define MS  (B*S)          // 32768
#define KC  (2*H)          // 2048

#if defined(__CUDA_ARCH_FEAT_SM103_ALL) || defined(__CUDA_ARCH_FEAT_SM100_ALL)
#define HAS_TC 1
#else
#define HAS_TC 0
#endif

// ---------------- scratch ----------------
__device__ float g_prev[B*H];
__device__ float g_gi[B*TH];
__device__ float g_gh[B*TH];
__device__ float g_scoreg[(size_t)B*V];
__device__ float g_scorec[B*S];
__device__ float g_scorec_raw[B*S];
__device__ float g_rowmax[B];
__device__ float g_rowsum[B];
__device__ __nv_bfloat16 g_Wc_hi[H*KC];
__device__ __nv_bfloat16 g_Wc_lo[H*KC];
__device__ __nv_bfloat16 g_x_hi[B*KX],    g_x_lo[B*KX];
__device__ __nv_bfloat16 g_prev_hi[B*H],  g_prev_lo[B*H];
__device__ __nv_bfloat16 g_state_hi[B*H], g_state_lo[B*H];

__device__ __forceinline__ void split_bf16(float x, uint16_t& h, uint16_t& l){
    __nv_bfloat16 bh = __float2bfloat16_rn(x);
    __nv_bfloat16 bl = __float2bfloat16_rn(x - __bfloat162float(bh));
    h = __bfloat16_as_ushort(bh);
    l = __bfloat16_as_ushort(bl);
}

// ---------------- tcgen05 plumbing ----------------
#if HAS_TC
__device__ __forceinline__ uint32_t smem_u32(const void* p){
    uint32_t a;
    asm("{ .reg .u64 t; cvta.to.shared.u64 t, %1; cvt.u32.u64 %0, t; }" : "=r"(a) : "l"(p));
    return a;
}
__device__ __forceinline__ uint32_t elect_one(){
    uint32_t p;
    asm volatile("{ .reg .pred p; elect.sync _|p, 0xFFFFFFFF; selp.b32 %0, 1, 0, p; }" : "=r"(p));
    return p;
}
#define TC_ALLOC(saddr, n)  asm volatile("tcgen05.alloc.cta_group::1.sync.aligned.shared::cta.b32 [%0], %1;" :: "r"((uint32_t)(saddr)), "r"((uint32_t)(n)) : "memory")
#define TC_DEALLOC(t, n)    asm volatile("tcgen05.dealloc.cta_group::1.sync.aligned.b32 %0, %1;" :: "r"(t), "r"((uint32_t)(n)))
#define TC_RELINQ()         asm volatile("tcgen05.relinquish_alloc_permit.cta_group::1.sync.aligned;")
#define TC_COMMIT(mb)       asm volatile("tcgen05.commit.cta_group::1.mbarrier::arrive::one.shared::cluster.b64 [%0];" :: "r"((uint32_t)(mb)) : "memory")
#define TC_FENCE_AFTER()    asm volatile("tcgen05.fence::after_thread_sync;" ::: "memory")
#define TC_FENCE_BEFORE()   asm volatile("tcgen05.fence::before_thread_sync;" ::: "memory")
#define TC_WAIT_LD()        asm volatile("tcgen05.wait::ld.sync.aligned;" ::: "memory")
#define MBAR_INIT(mb, cnt)  asm volatile("mbarrier.init.shared.b64 [%0], %1;" :: "r"((uint32_t)(mb)), "r"((uint32_t)(cnt)) : "memory")
#define MBAR_EXPECT_TX(mb, bytes) asm volatile("mbarrier.arrive.expect_tx.shared.b64 _, [%0], %1;" :: "r"((uint32_t)(mb)), "r"((uint32_t)(bytes)) : "memory")
#define TMA_LOAD_2D(sa, mp, cx, cy, mb) \
    asm volatile("cp.async.bulk.tensor.2d.shared::cta.global.tile.mbarrier::complete_tx::bytes [%0], [%1, {%2, %3}], [%4];" \
        :: "r"((uint32_t)(sa)), "l"(mp), "r"((int)(cx)), "r"((int)(cy)), "r"((uint32_t)(mb)) : "memory")
#define MBAR_WAIT(mb, ph) do { \
    uint32_t _m = (uint32_t)(mb); uint32_t _p = (uint32_t)(ph); uint32_t _d; \
    asm volatile("{ .reg .pred p; mbarrier.try_wait.parity.acquire.cta.shared::cta.b64 p, [%1], %2; selp.b32 %0, 1, 0, p; }" \
        : "=r"(_d) : "r"(_m), "r"(_p) : "memory"); \
    if (!_d) { \
        asm volatile("{ .reg .pred P1; WL_%=: mbarrier.try_wait.parity.acquire.cta.shared::cta.b64 P1, [%0], %1, 0x989680; @P1 bra.uni WD_%=; bra.uni WL_%=; WD_%=: }" \
            :: "r"(_m), "r"(_p) : "memory"); \
    } } while(0)

static constexpr uint64_t SMEM_DESC_BASE_SW128 =
    (uint64_t(2)  << 61) | (uint64_t(1) << 46) | (uint64_t(64) << 32) | (uint64_t(1) << 16);
#define MK_DESC(a) (SMEM_DESC_BASE_SW128 | ((uint64_t)((a) >> 4) & 0x3FFF))

#define TC_LD_X32(r, t) \
    asm volatile("tcgen05.ld.sync.aligned.32x32b.x32.b32 " \
        "{%0,%1,%2,%3,%4,%5,%6,%7,%8,%9,%10,%11,%12,%13,%14,%15," \
        "%16,%17,%18,%19,%20,%21,%22,%23,%24,%25,%26,%27,%28,%29,%30,%31}, [%32];" \
        : "=r"((r)[0]),"=r"((r)[1]),"=r"((r)[2]),"=r"((r)[3]),"=r"((r)[4]),"=r"((r)[5]),"=r"((r)[6]),"=r"((r)[7]), \
          "=r"((r)[8]),"=r"((r)[9]),"=r"((r)[10]),"=r"((r)[11]),"=r"((r)[12]),"=r"((r)[13]),"=r"((r)[14]),"=r"((r)[15]), \
          "=r"((r)[16]),"=r"((r)[17]),"=r"((r)[18]),"=r"((r)[19]),"=r"((r)[20]),"=r"((r)[21]),"=r"((r)[22]),"=r"((r)[23]), \
          "=r"((r)[24]),"=r"((r)[25]),"=r"((r)[26]),"=r"((r)[27]),"=r"((r)[28]),"=r"((r)[29]),"=r"((r)[30]),"=r"((r)[31]) \
        : "r"(t))

__device__ __forceinline__ void mma_f16_ss(uint32_t d, uint64_t a, uint64_t b, uint32_t idesc, uint32_t en){
    asm volatile("{ .reg .pred p; setp.ne.u32 p, %4, 0;"
        " tcgen05.mma.cta_group::1.kind::f16 [%0], %1, %2, %3, {%5,%5,%5,%5}, p; }"
        :: "r"(d), "l"(a), "l"(b), "r"(idesc), "r"(en), "r"(0u) : "memory");
}
#endif // HAS_TC

// ==== big fused GEMM: cg1, SINGLE-stage, 2 CTAs/SM, TMA B, reg-prefetched A ====
#define HDR_SC 4096
#define T_AH (HDR_SC + 0)
#define T_AL (HDR_SC + 16384)
#define T_BH (HDR_SC + 32768)
#define T_BL (HDR_SC + 65536)
#define SMEM_TC 102400           // 100 KB -> 2 CTAs/SM
#define NCHUNK_SC 32
#define SC_THREADS 512
#define MB_FULL  8
#define MB_EMPTY 16

__global__ void __launch_bounds__(SC_THREADS, 2)
k_tc_sc(const float* __restrict__ A,
        const __grid_constant__ CUtensorMap mapBh,
        const __grid_constant__ CUtensorMap mapBl,
        const float* __restrict__ bias){
#if HAS_TC
    extern __shared__ char smem[];
    uint32_t sb = smem_u32(smem);
    int tid = threadIdx.x, wid = tid >> 5, lid = tid & 31;
    int n0 = blockIdx.x * 256;
    int m0 = blockIdx.y * 128;
    int b  = m0 >> 9;
    float* s_state = (float*)(smem + 64);
    float* s_bias  = (float*)(smem + 64 + 1024);

    if (wid == 0){ TC_ALLOC(sb + 0, 256); TC_RELINQ(); }
    if (tid == 0){
        MBAR_INIT(sb + MB_FULL, 1);
        MBAR_INIT(sb + MB_EMPTY, 1);
    }
    if (tid < 256){
        int hb = b*TH;
        int hh = n0 + tid;
        float r = 1.f/(1.f + expf(-(g_gi[hb + hh]       + g_gh[hb + hh])));
        float z = 1.f/(1.f + expf(-(g_gi[hb + H + hh]   + g_gh[hb + H + hh])));
        float n = tanhf(g_gi[hb + 2*H + hh] + r*g_gh[hb + 2*H + hh]);
        s_state[tid] = (1.f - z)*n + z*g_prev[b*H + hh];
        s_bias[tid]  = bias[n0 + tid];
    }
    __syncthreads();
    uint32_t tmem;
    asm volatile("ld.shared.b32 %0, [%1];" : "=r"(tmem) : "r"(sb));

    // per-thread A slice coordinates (fixed across chunks): 4 float4 groups
    int rowi[4], gi4[4];
    #pragma unroll
    for (int it = 0; it < 4; it++){
        int i = tid + it*SC_THREADS;
        rowi[it] = i >> 4; gi4[it] = i & 15;
    }

    auto prefetch_A = [&](int c, float4* pf){
        int k0 = c * 64;
        #pragma unroll
        for (int it = 0; it < 4; it++)
            pf[it] = *(const float4*)(A + (size_t)(m0+rowi[it])*KC + k0 + gi4[it]*4);
    };
    auto store_A = [&](const float4* pf){
        #pragma unroll
        for (int it = 0; it < 4; it++){
            float4 a4 = pf[it];
            uint16_t h0,h1,h2,h3,l0,l1,l2,l3;
            split_bf16(a4.x,h0,l0); split_bf16(a4.y,h1,l1);
            split_bf16(a4.z,h2,l2); split_bf16(a4.w,h3,l3);
            uint2 hv = make_uint2((uint32_t)h0 | ((uint32_t)h1<<16), (uint32_t)h2 | ((uint32_t)h3<<16));
            uint2 lv = make_uint2((uint32_t)l0 | ((uint32_t)l1<<16), (uint32_t)l2 | ((uint32_t)l3<<16));
            uint32_t off = (uint32_t)(rowi[it]*128 + gi4[it]*8);
            uint32_t sw  = off ^ ((off >> 3) & 0x70);
            *(uint2*)(smem + T_AH + sw) = hv;
            *(uint2*)(smem + T_AL + sw) = lv;
        }
    };

    const uint32_t idesc = (1u<<4) | (1u<<7) | (1u<<10) | (32u<<17) | (8u<<24);
    float4 pf[4];
    prefetch_A(0, pf);
    int phf = 0, phe = 0;

    for (int c = 0; c < NCHUNK_SC; c++){
        if (c > 0){ MBAR_WAIT(sb + MB_EMPTY, phe); phe ^= 1; }   // MMA c-1 done -> buffer free
        if (wid == 1 && elect_one()){
            int k0 = c * 64;
            MBAR_EXPECT_TX(sb + MB_FULL, 65536);
            TMA_LOAD_2D(sb + T_BH, &mapBh, k0, n0, sb + MB_FULL);
            TMA_LOAD_2D(sb + T_BL, &mapBl, k0, n0, sb + MB_FULL);
        }
        store_A(pf);                                  // convert + STS only (regs ready)
        asm volatile("fence.proxy.async.shared::cta;" ::: "memory");
        __syncthreads();
        if (c + 1 < NCHUNK_SC) prefetch_A(c + 1, pf); // LDGs overlap MMA of chunk c
        if (wid == 0 && elect_one()){
            MBAR_WAIT(sb + MB_FULL, phf); phf ^= 1;   // B (TMA) ready
            uint64_t dAh = MK_DESC(sb + T_AH);
            uint64_t dAl = MK_DESC(sb + T_AL);
            uint64_t dBh = MK_DESC(sb + T_BH);
            uint64_t dBl = MK_DESC(sb + T_BL);
            #pragma unroll
            for (int ks = 0; ks < 4; ks++){
                uint64_t o = (uint64_t)(ks*2);
                mma_f16_ss(tmem, dAh + o, dBh + o, idesc, (c==0 && ks==0) ? 0u : 1u);
                mma_f16_ss(tmem, dAh + o, dBl + o, idesc, 1u);
                mma_f16_ss(tmem, dAl + o, dBh + o, idesc, 1u);
            }
            TC_COMMIT(sb + MB_EMPTY);
        }
    }
    MBAR_WAIT(sb + MB_EMPTY, phe);
    TC_FENCE_AFTER();

    if (wid < 4){
        float acc = 0.f;
        #pragma unroll
        for (int c0 = 0; c0 < 256; c0 += 32){
            uint32_t r[32];
            TC_LD_X32(r, tmem + c0);
            TC_WAIT_LD();
            #pragma unroll
            for (int j = 0; j < 32; j++)
                acc += tanhf(__uint_as_float(r[j]) + s_bias[c0+j]) * s_state[c0+j];
        }
        TC_FENCE_BEFORE();
        atomicAdd(&g_scorec_raw[m0 + wid*32 + lid], acc);
    }
    __syncthreads();
    if (wid == 0) TC_DEALLOC(tmem, 256);
#endif
}

// ============ generic tc GEMM (unchanged) ============
#define HDR_W 1024
#define WSTG 49152
#define W_AH 0
#define W_AL 16384
#define W_BH 32768
#define W_BL 40960
#define WT_OFF(stg, t) (HDR_W + (uint32_t)(stg)*WSTG + (uint32_t)(t))
#define SMEM_TW (HDR_W + 2*WSTG)

__global__ void __launch_bounds__(256, 1) k_tcW(const float* __restrict__ W,
        const __nv_bfloat16* __restrict__ act_hi, const __nv_bfloat16* __restrict__ act_lo,
        float* __restrict__ out, int Nw, int K, int kpc, int ldO,
        const float* __restrict__ obias){
#if HAS_TC
    extern __shared__ char smem[];
    uint32_t sb = smem_u32(smem);
    int tid = threadIdx.x, wid = tid >> 5, lid = tid & 31;
    int m0 = blockIdx.x * 128;
    int k_base = blockIdx.y * kpc * 64;

    if (wid == 0){ TC_ALLOC(sb + 0, 64); TC_RELINQ(); }
    if (tid == 0){ MBAR_INIT(sb + 8, 1); MBAR_INIT(sb + 16, 1); }
    __syncthreads();
    uint32_t tmem;
    asm volatile("ld.shared.b32 %0, [%1];" : "=r"(tmem) : "r"(sb));

    auto load_chunk = [&](int c, int stg){
        int k0 = k_base + c * 64;
        #pragma unroll
        for (int it = 0; it < 8; it++){
            int i = tid + it*256;
            int row = i >> 4, g = i & 15;
            float4 a4 = make_float4(0.f,0.f,0.f,0.f);
            if (m0 + row < Nw) a4 = *(const float4*)(W + (size_t)(m0+row)*K + k0 + g*4);
            uint16_t h0,h1,h2,h3,l0,l1,l2,l3;
            split_bf16(a4.x,h0,l0); split_bf16(a4.y,h1,l1);
            split_bf16(a4.z,h2,l2); split_bf16(a4.w,h3,l3);
            uint2 hv = make_uint2((uint32_t)h0 | ((uint32_t)h1<<16), (uint32_t)h2 | ((uint32_t)h3<<16));
            uint2 lv = make_uint2((uint32_t)l0 | ((uint32_t)l1<<16), (uint32_t)l2 | ((uint32_t)l3<<16));
            uint32_t off = (uint32_t)(row*128 + g*8);
            uint32_t sw  = off ^ ((off >> 3) & 0x70);
            *(uint2*)(smem + WT_OFF(stg, W_AH) + sw) = hv;
            *(uint2*)(smem + WT_OFF(stg, W_AL) + sw) = lv;
        }
        #pragma unroll
        for (int it = 0; it < 2; it++){
            int i = tid + it*256;
            int row = i >> 3, g = i & 7;
            size_t base = ((size_t)row*K + k0) * 2;
            uint4 h4 = *(const uint4*)((const char*)act_hi + base + g*16);
            uint4 l4 = *(const uint4*)((const char*)act_lo + base + g*16);
            uint32_t off = (uint32_t)(row*128 + g*16);
            uint32_t sw  = off ^ ((off >> 3) & 0x70);
            *(uint4*)(smem + WT_OFF(stg, W_BH) + sw) = h4;
            *(uint4*)(smem + WT_OFF(stg, W_BL) + sw) = l4;
        }
    };

    load_chunk(0, 0);
    asm volatile("fence.proxy.async.shared::cta;" ::: "memory");
    __syncthreads();

    const uint32_t idesc = (1u<<4) | (1u<<7) | (1u<<10) | (8u<<17) | (8u<<24);   // N=64, M=128
    int ph[2] = {0, 0};

    for (int c = 0; c < kpc; c++){
        int stg = c & 1;
        if (wid == 0 && elect_one()){
            uint64_t dAh = MK_DESC(sb + WT_OFF(stg, W_AH));
            uint64_t dAl = MK_DESC(sb + WT_OFF(stg, W_AL));
            uint64_t dBh = MK_DESC(sb + WT_OFF(stg, W_BH));
            uint64_t dBl = MK_DESC(sb + WT_OFF(stg, W_BL));
            #pragma unroll
            for (int ks = 0; ks < 4; ks++){
                uint64_t o = (uint64_t)(ks*2);
                mma_f16_ss(tmem, dAh + o, dBh + o, idesc, (c==0 && ks==0) ? 0u : 1u);
                mma_f16_ss(tmem, dAh + o, dBl + o, idesc, 1u);
                mma_f16_ss(tmem, dAl + o, dBh + o, idesc, 1u);
            }
            TC_COMMIT(sb + 8 + stg*8);
        }
        if (c + 1 < kpc){
            int nst = stg ^ 1;
            if (c >= 1){ MBAR_WAIT(sb + 8 + nst*8, ph[nst]); ph[nst] ^= 1; }
            load_chunk(c + 1, nst);
            asm volatile("fence.proxy.async.shared::cta;" ::: "memory");
            __syncthreads();
        }
    }
    MBAR_WAIT(sb + 8 + ((kpc-1)&1)*8, ph[(kpc-1)&1]);
    TC_FENCE_AFTER();

    if (wid < 4){
        uint32_t r0[32], r1[32];
        TC_LD_X32(r0, tmem);
        TC_LD_X32(r1, tmem + 32);
        TC_WAIT_LD();
        TC_FENCE_BEFORE();
        int m = m0 + wid*32 + lid;
        if (m < Nw){
            if (obias){
                float bv = obias[m];
                #pragma unroll
                for (int c = 0; c < 32; c++)
                    out[(size_t)c*ldO + m] = __uint_as_float(r0[c]) + bv;
                #pragma unroll
                for (int c = 0; c < 32; c++)
                    out[(size_t)(c+32)*ldO + m] = __uint_as_float(r1[c]) + bv;
            } else {
                #pragma unroll
                for (int c = 0; c < 32; c++)
                    atomicAdd(out + (size_t)c*ldO + m, __uint_as_float(r0[c]));
                #pragma unroll
                for (int c = 0; c < 32; c++)
                    atomicAdd(out + (size_t)(c+32)*ldO + m, __uint_as_float(r1[c]));
            }
        }
    }
    __syncthreads();
    if (wid == 0) TC_DEALLOC(tmem, 64);
#endif
}

// ---------------- fused prep ----------------
__global__ void k_prep(const int* __restrict__ input_idx, const float* __restrict__ embed,
                       const float* __restrict__ weighted, const float* __restrict__ prev_state,
                       const float* __restrict__ encoded, const float* __restrict__ Ws_w,
                       const float* __restrict__ Ws_b, const float* __restrict__ bi,
                       const float* __restrict__ bh, const float* __restrict__ Wc,
                       const int* __restrict__ order, int has_order){
    int i = blockIdx.x*blockDim.x + threadIdx.x;
    int ord = has_order ? *order : 1;
    {
        int j = i % TH;
        g_gi[i] = bi[j];
        g_gh[i] = bh[j];
    }
    if (i < B*KX){
        int b = i / KX, j = i - b*KX;
        float v;
        if (j < E) v = embed[(size_t)input_idx[b]*E + j];
        else       v = ord ? weighted[b*(2*H) + (j - E)] : 0.f;
        uint16_t h, l; split_bf16(v, h, l);
        g_x_hi[i] = __ushort_as_bfloat16(h);
        g_x_lo[i] = __ushort_as_bfloat16(l);
    }
    if (i < B*H){
        float v;
        if (ord){
            v = prev_state[i];
        } else {
            int b = i >> 10, h = i & (H-1);
            const float* e = encoded + ((size_t)b*S + (S-1))*(2*H);
            const float* w = Ws_w + (size_t)h*(2*H);
            float s = Ws_b[h];
            for (int k = 0; k < 2*H; k++) s = fmaf(e[k], w[k], s);
            v = s;
        }
        g_prev[i] = v;
        uint16_t h16, l16; split_bf16(v, h16, l16);
        g_prev_hi[i] = __ushort_as_bfloat16(h16);
        g_prev_lo[i] = __ushort_as_bfloat16(l16);
    }
    if (i < B*S) g_scorec_raw[i] = 0.f;
    for (int t = i; t < (H*KC)/4; t += B*TH){
        size_t e = (size_t)t*4;
        float4 w = *(const float4*)(Wc + e);
        uint16_t h0,h1,h2,h3,l0,l1,l2,l3;
        split_bf16(w.x,h0,l0); split_bf16(w.y,h1,l1);
        split_bf16(w.z,h2,l2); split_bf16(w.w,h3,l3);
        uint2 hv = make_uint2((uint32_t)h0 | ((uint32_t)h1<<16), (uint32_t)h2 | ((uint32_t)h3<<16));
        uint2 lv = make_uint2((uint32_t)l0 | ((uint32_t)l1<<16), (uint32_t)l2 | ((uint32_t)l3<<16));
        *(uint2*)((char*)g_Wc_hi + e*2) = hv;
        *(uint2*)((char*)g_Wc_lo + e*2) = lv;
    }
}

// ---------------- GRU combine ----------------
__global__ void k_combine(float* __restrict__ out_state){
    int i = blockIdx.x*blockDim.x + threadIdx.x;
    if (i >= B*H) return;
    int b = i >> 10, h = i & (H-1);
    const float* gi = g_gi + b*TH;
    const float* gh = g_gh + b*TH;
    float r = 1.f/(1.f + expf(-(gi[h]        + gh[h])));
    float z = 1.f/(1.f + expf(-(gi[H + h]    + gh[H + h])));
    float n = tanhf(gi[2*H + h] + r*gh[2*H + h]);
    float st = (1.f - z)*n + z*g_prev[i];
    out_state[i] = st;
    uint16_t h16, l16; split_bf16(st, h16, l16);
    g_state_hi[i] = __ushort_as_bfloat16(h16);
    g_state_lo[i] = __ushort_as_bfloat16(l16);
}

// ---------------- finalize score_c ----------------
__global__ void k_scorec_fin(const int* __restrict__ encoded_idx){
    int m = blockIdx.x*blockDim.x + threadIdx.x;
    float v = tanhf(g_scorec_raw[m]);
    if (encoded_idx[m] == 0) v -= 1000.f;
    g_scorec[m] = v;
}

// ---------------- softmax stats / writeout / tail ----------------
__global__ void k_rowstats(){
    int b = blockIdx.x;
    __shared__ float red[256];
    const float* sg = g_scoreg + (size_t)b*V;
    const float* sc = g_scorec + b*S;
    float mx = -1e30f;
    for (int i = threadIdx.x; i < V; i += 256) mx = fmaxf(mx, sg[i]);
    for (int i = threadIdx.x; i < S; i += 256) mx = fmaxf(mx, sc[i]);
    red[threadIdx.x] = mx; __syncthreads();
    for (int st = 128; st; st >>= 1){
        if (threadIdx.x < st) red[threadIdx.x] = fmaxf(red[threadIdx.x], red[threadIdx.x+st]);
        __syncthreads();
    }
    mx = red[0];
    __syncthreads();
    float sm = 0.f;
    for (int i = threadIdx.x; i < V; i += 256) sm += expf(sg[i] - mx);
    for (int i = threadIdx.x; i < S; i += 256) sm += expf(sc[i] - mx);
    red[threadIdx.x] = sm; __syncthreads();
    for (int st = 128; st; st >>= 1){
        if (threadIdx.x < st) red[threadIdx.x] += red[threadIdx.x+st];
        __syncthreads();
    }
    if (threadIdx.x == 0){ g_rowmax[b] = mx; g_rowsum[b] = red[0]; }
}

__global__ void k_writeout(float* __restrict__ out){
    long long i = (long long)blockIdx.x*256 + threadIdx.x;
    if (i >= (long long)B*OUTW) return;
    int b = (int)(i / OUTW);
    int c = (int)(i - (long long)b*OUTW);
    float v;
    if (c < V) v = expf(g_scoreg[(size_t)b*V + c] - g_rowmax[b]) / g_rowsum[b];
    else       v = 1e-4f;
    out[i] = v;
}

__global__ void k_tail(float* __restrict__ out, float* __restrict__ out_w,
                       const int* __restrict__ encoded_idx, const int* __restrict__ input_idx,
                       const float* __restrict__ encoded){
    int b = blockIdx.x;
    __shared__ float pc[S];
    __shared__ float attn[S];
    __shared__ int   icnt[256];
    float mx  = g_rowmax[b];
    float inv = 1.f / g_rowsum[b];
    int target = input_idx[b];
    int c = 0;
    for (int s = threadIdx.x; s < S; s += 256){
        float p = expf(g_scorec[b*S + s] - mx) * inv;
        pc[s] = p;
        if (encoded_idx[b*S + s] == target) c++;
    }
    icnt[threadIdx.x] = c; __syncthreads();
    for (int st = 128; st; st >>= 1){
        if (threadIdx.x < st) icnt[threadIdx.x] += icnt[threadIdx.x+st];
        __syncthreads();
    }
    int ssum = icnt[0];
    float scale = (ssum > 1) ? 1.f/(float)ssum : 1.f;
    for (int s = threadIdx.x; s < S; s += 256){
        int idx = encoded_idx[b*S + s];
        atomicAdd(&out[(size_t)b*OUTW + idx], pc[s]);
        attn[s] = (idx == target) ? pc[s]*scale : 0.f;
    }
    __syncthreads();
    float acc[8] = {0.f,0.f,0.f,0.f,0.f,0.f,0.f,0.f};
    const float* eb = encoded + (size_t)b*S*(2*H);
    for (int s = 0; s < S; s++){
        float a = attn[s];
        if (a != 0.f){
            const float* er = eb + (size_t)s*(2*H);
            #pragma unroll
            for (int j = 0; j < 8; j++)
                acc[j] = fmaf(a, er[threadIdx.x + j*256], acc[j]);
        }
    }
    #pragma unroll
    for (int j = 0; j < 8; j++)
        out_w[b*(2*H) + threadIdx.x + j*256] = acc[j];
}

// ---------------- launch ----------------
typedef CUresult (*tme_fn_t)(CUtensorMap*, CUtensorMapDataType, cuuint32_t, void*,
                             const cuuint64_t*, const cuuint64_t*, const cuuint32_t*,
                             const cuuint32_t*, CUtensorMapInterleave, CUtensorMapSwizzle,
                             CUtensorMapL2promotion, CUtensorMapFloatOOBfill);

extern "C" void kernel_launch(void* const* d_in, const int* in_sizes, int n_in,
                              void* d_out, int out_size){
    const int*   input_idx   = (const int*)  d_in[0];
    const float* encoded     = (const float*)d_in[1];
    const int*   encoded_idx = (const int*)  d_in[2];
    const float* prev_state  = (const float*)d_in[3];
    const float* weighted    = (const float*)d_in[4];
    int off = 0;
    const int* order = nullptr;
    if (n_in >= 17 && in_sizes[5] == 1){ order = (const int*)d_in[5]; off = 1; }
    const float* embed  = (const float*)d_in[5+off];
    const float* gru_wi = (const float*)d_in[6+off];
    const float* gru_wh = (const float*)d_in[7+off];
    const float* gru_bi = (const float*)d_in[8+off];
    const float* gru_bh = (const float*)d_in[9+off];
    const float* Ws_w   = (const float*)d_in[10+off];
    const float* Ws_b   = (const float*)d_in[11+off];
    const float* Wg_w   = (const float*)d_in[12+off];
    const float* Wg_b   = (const float*)d_in[13+off];
    const float* Wc_w   = (const float*)d_in[14+off];
    const float* Wc_b   = (const float*)d_in[15+off];
    int has_order = (order != nullptr);
    if (!order) order = input_idx;

    float* out       = (float*)d_out;
    float* out_state = out + (size_t)B*OUTW;
    float* out_w     = out_state + (size_t)B*H;

    static float *p_gi = nullptr, *p_gh, *p_scoreg;
    static __nv_bfloat16 *p_Bh, *p_Bl, *p_xh, *p_xl, *p_ph, *p_pl, *p_sh, *p_sl;
    static CUtensorMap mapBh, mapBl;
    if (!p_gi){
        cudaGetSymbolAddress((void**)&p_gi,     g_gi);
        cudaGetSymbolAddress((void**)&p_gh,     g_gh);
        cudaGetSymbolAddress((void**)&p_scoreg, g_scoreg);
        cudaGetSymbolAddress((void**)&p_Bh,     g_Wc_hi);
        cudaGetSymbolAddress((void**)&p_Bl,     g_Wc_lo);
        cudaGetSymbolAddress((void**)&p_xh,     g_x_hi);
        cudaGetSymbolAddress((void**)&p_xl,     g_x_lo);
        cudaGetSymbolAddress((void**)&p_ph,     g_prev_hi);
        cudaGetSymbolAddress((void**)&p_pl,     g_prev_lo);
        cudaGetSymbolAddress((void**)&p_sh,     g_state_hi);
        cudaGetSymbolAddress((void**)&p_sl,     g_state_lo);
        cudaFuncSetAttribute(k_tc_sc, cudaFuncAttributeMaxDynamicSharedMemorySize, SMEM_TC);
        cudaFuncSetAttribute(k_tcW,   cudaFuncAttributeMaxDynamicSharedMemorySize, SMEM_TW);

        void* fn = nullptr;
        cudaDriverEntryPointQueryResult qr;
        cudaGetDriverEntryPointByVersion("cuTensorMapEncodeTiled", &fn, 12000,
                                         cudaEnableDefault, &qr);
        tme_fn_t enc = (tme_fn_t)fn;
        cuuint64_t dims[2]    = {(cuuint64_t)KC, (cuuint64_t)H};
        cuuint64_t strides[1] = {(cuuint64_t)KC * 2};
        cuuint32_t box[2]     = {64, 256};
        cuuint32_t es[2]      = {1, 1};
        enc(&mapBh, CU_TENSOR_MAP_DATA_TYPE_BFLOAT16, 2, p_Bh, dims, strides, box, es,
            CU_TENSOR_MAP_INTERLEAVE_NONE, CU_TENSOR_MAP_SWIZZLE_128B,
            CU_TENSOR_MAP_L2_PROMOTION_L2_128B, CU_TENSOR_MAP_FLOAT_OOB_FILL_NONE);
        enc(&mapBl, CU_TENSOR_MAP_DATA_TYPE_BFLOAT16, 2, p_Bl, dims, strides, box, es,
            CU_TENSOR_MAP_INTERLEAVE_NONE, CU_TENSOR_MAP_SWIZZLE_128B,
            CU_TENSOR_MAP_L2_PROMOTION_L2_128B, CU_TENSOR_MAP_FLOAT_OOB_FILL_NONE);
    }

    // launch 0: fused prep (incl Wc conversion)
    k_prep<<<(B*TH)/256, 256>>>(input_idx, embed, weighted, prev_state, encoded,
                                Ws_w, Ws_b, gru_bi, gru_bh, Wc_w, order, has_order);
    // 1, 2: GRU gate GEMMs
    k_tcW<<<dim3(TH/128, 5), 256, SMEM_TW>>>(gru_wi, p_xh, p_xl, p_gi, TH, KX, 8, TH, nullptr);
    k_tcW<<<dim3(TH/128, 4), 256, SMEM_TW>>>(gru_wh, p_ph, p_pl, p_gh, TH, H,  4, TH, nullptr);
    // 3: big fused GEMM (single-stage, 2 CTA/SM) — ncu capture lands here
    k_tc_sc<<<dim3(H/256, MS/128), SC_THREADS, SMEM_TC>>>(encoded, mapBh, mapBl, Wc_b);
    // 4: combine
    k_combine<<<(B*H)/256, 256>>>(out_state);
    // 5: score_g
    k_tcW<<<dim3((V+127)/128, 1), 256, SMEM_TW>>>(Wg_w, p_sh, p_sl, p_scoreg, V, H, H/64, V, Wg_b);

    k_scorec_fin<<<MS/256, 256>>>(encoded_idx);
    k_rowstats<<<B, 256>>>();
    k_writeout<<<((long long)B*OUTW + 255)/256, 256>>>(out);
    k_tail    <<<B, 256>>>(out, out_w, encoded_idx, input_idx, encoded);
}

// round 17
// speedup vs baseline: 2.1462x; 1.0620x over previous
#include <cuda_runtime.h>
#include <cuda.h>
#include <cuda_bf16.h>
#include <cstdint>

#define B   64
#define S   512
#define V   50257
#define E   512
#define H   1024
#define OOV 12
#define OUTW (V + OOV)     // 50269
#define KX  (E + 2*H)      // 2560
#define TH  (3*H)          // 3072
#define MS  (B*S)          // 32768
#define KC  (2*H)          // 2048

#if defined(__CUDA_ARCH_FEAT_SM103_ALL) || defined(__CUDA_ARCH_FEAT_SM100_ALL)
#define HAS_TC 1
#else
#define HAS_TC 0
#endif

// ---------------- scratch ----------------
__device__ float g_prev[B*H];
__device__ float g_gi[B*TH];
__device__ float g_gh[B*TH];
__device__ float g_scoreg[(size_t)B*V];
__device__ float g_scorec[B*S];
__device__ float g_scorec_raw[B*S];
__device__ float g_rowmax[B];
__device__ float g_rowsum[B];
__device__ __nv_bfloat16 g_Wc_hi[H*KC];
__device__ __nv_bfloat16 g_Wc_lo[H*KC];
__device__ __nv_bfloat16 g_x_hi[B*KX],    g_x_lo[B*KX];
__device__ __nv_bfloat16 g_prev_hi[B*H],  g_prev_lo[B*H];
__device__ __nv_bfloat16 g_state_hi[B*H], g_state_lo[B*H];

__device__ __forceinline__ void split_bf16(float x, uint16_t& h, uint16_t& l){
    __nv_bfloat16 bh = __float2bfloat16_rn(x);
    __nv_bfloat16 bl = __float2bfloat16_rn(x - __bfloat162float(bh));
    h = __bfloat16_as_ushort(bh);
    l = __bfloat16_as_ushort(bl);
}

// ---------------- tcgen05 plumbing ----------------
#if HAS_TC
__device__ __forceinline__ uint32_t smem_u32(const void* p){
    uint32_t a;
    asm("{ .reg .u64 t; cvta.to.shared.u64 t, %1; cvt.u32.u64 %0, t; }" : "=r"(a) : "l"(p));
    return a;
}
__device__ __forceinline__ uint32_t elect_one(){
    uint32_t p;
    asm volatile("{ .reg .pred p; elect.sync _|p, 0xFFFFFFFF; selp.b32 %0, 1, 0, p; }" : "=r"(p));
    return p;
}
#define TC_ALLOC(saddr, n)  asm volatile("tcgen05.alloc.cta_group::1.sync.aligned.shared::cta.b32 [%0], %1;" :: "r"((uint32_t)(saddr)), "r"((uint32_t)(n)) : "memory")
#define TC_DEALLOC(t, n)    asm volatile("tcgen05.dealloc.cta_group::1.sync.aligned.b32 %0, %1;" :: "r"(t), "r"((uint32_t)(n)))
#define TC_RELINQ()         asm volatile("tcgen05.relinquish_alloc_permit.cta_group::1.sync.aligned;")
#define TC_COMMIT(mb)       asm volatile("tcgen05.commit.cta_group::1.mbarrier::arrive::one.shared::cluster.b64 [%0];" :: "r"((uint32_t)(mb)) : "memory")
#define TC_FENCE_AFTER()    asm volatile("tcgen05.fence::after_thread_sync;" ::: "memory")
#define TC_FENCE_BEFORE()   asm volatile("tcgen05.fence::before_thread_sync;" ::: "memory")
#define TC_WAIT_LD()        asm volatile("tcgen05.wait::ld.sync.aligned;" ::: "memory")
#define MBAR_INIT(mb, cnt)  asm volatile("mbarrier.init.shared.b64 [%0], %1;" :: "r"((uint32_t)(mb)), "r"((uint32_t)(cnt)) : "memory")
#define MBAR_EXPECT_TX(mb, bytes) asm volatile("mbarrier.arrive.expect_tx.shared.b64 _, [%0], %1;" :: "r"((uint32_t)(mb)), "r"((uint32_t)(bytes)) : "memory")
#define TMA_LOAD_2D(sa, mp, cx, cy, mb) \
    asm volatile("cp.async.bulk.tensor.2d.shared::cta.global.tile.mbarrier::complete_tx::bytes [%0], [%1, {%2, %3}], [%4];" \
        :: "r"((uint32_t)(sa)), "l"(mp), "r"((int)(cx)), "r"((int)(cy)), "r"((uint32_t)(mb)) : "memory")
#define MBAR_WAIT(mb, ph) do { \
    uint32_t _m = (uint32_t)(mb); uint32_t _p = (uint32_t)(ph); uint32_t _d; \
    asm volatile("{ .reg .pred p; mbarrier.try_wait.parity.acquire.cta.shared::cta.b64 p, [%1], %2; selp.b32 %0, 1, 0, p; }" \
        : "=r"(_d) : "r"(_m), "r"(_p) : "memory"); \
    if (!_d) { \
        asm volatile("{ .reg .pred P1; WL_%=: mbarrier.try_wait.parity.acquire.cta.shared::cta.b64 P1, [%0], %1, 0x989680; @P1 bra.uni WD_%=; bra.uni WL_%=; WD_%=: }" \
            :: "r"(_m), "r"(_p) : "memory"); \
    } } while(0)

static constexpr uint64_t SMEM_DESC_BASE_SW128 =
    (uint64_t(2)  << 61) | (uint64_t(1) << 46) | (uint64_t(64) << 32) | (uint64_t(1) << 16);
#define MK_DESC(a) (SMEM_DESC_BASE_SW128 | ((uint64_t)((a) >> 4) & 0x3FFF))

#define TC_LD_X32(r, t) \
    asm volatile("tcgen05.ld.sync.aligned.32x32b.x32.b32 " \
        "{%0,%1,%2,%3,%4,%5,%6,%7,%8,%9,%10,%11,%12,%13,%14,%15," \
        "%16,%17,%18,%19,%20,%21,%22,%23,%24,%25,%26,%27,%28,%29,%30,%31}, [%32];" \
        : "=r"((r)[0]),"=r"((r)[1]),"=r"((r)[2]),"=r"((r)[3]),"=r"((r)[4]),"=r"((r)[5]),"=r"((r)[6]),"=r"((r)[7]), \
          "=r"((r)[8]),"=r"((r)[9]),"=r"((r)[10]),"=r"((r)[11]),"=r"((r)[12]),"=r"((r)[13]),"=r"((r)[14]),"=r"((r)[15]), \
          "=r"((r)[16]),"=r"((r)[17]),"=r"((r)[18]),"=r"((r)[19]),"=r"((r)[20]),"=r"((r)[21]),"=r"((r)[22]),"=r"((r)[23]), \
          "=r"((r)[24]),"=r"((r)[25]),"=r"((r)[26]),"=r"((r)[27]),"=r"((r)[28]),"=r"((r)[29]),"=r"((r)[30]),"=r"((r)[31]) \
        : "r"(t))

__device__ __forceinline__ void mma_f16_ss(uint32_t d, uint64_t a, uint64_t b, uint32_t idesc, uint32_t en){
    asm volatile("{ .reg .pred p; setp.ne.u32 p, %4, 0;"
        " tcgen05.mma.cta_group::1.kind::f16 [%0], %1, %2, %3, {%5,%5,%5,%5}, p; }"
        :: "r"(d), "l"(a), "l"(b), "r"(idesc), "r"(en), "r"(0u) : "memory");
}
#endif // HAS_TC

// ==== big fused GEMM: cg1, SINGLE-stage, 2 CTAs/SM, TMA B, reg-prefetched A ====
#define HDR_SC 4096
#define T_AH (HDR_SC + 0)
#define T_AL (HDR_SC + 16384)
#define T_BH (HDR_SC + 32768)
#define T_BL (HDR_SC + 65536)
#define SMEM_TC 102400           // 100 KB -> 2 CTAs/SM
#define NCHUNK_SC 32
#define SC_THREADS 512
#define MB_FULL  8
#define MB_EMPTY 16

__global__ void __launch_bounds__(SC_THREADS, 2)
k_tc_sc(const float* __restrict__ A,
        const __grid_constant__ CUtensorMap mapBh,
        const __grid_constant__ CUtensorMap mapBl,
        const float* __restrict__ bias){
#if HAS_TC
    extern __shared__ char smem[];
    uint32_t sb = smem_u32(smem);
    int tid = threadIdx.x, wid = tid >> 5, lid = tid & 31;
    int n0 = blockIdx.x * 256;
    int m0 = blockIdx.y * 128;
    int b  = m0 >> 9;
    float* s_state = (float*)(smem + 64);
    float* s_bias  = (float*)(smem + 64 + 1024);

    if (wid == 0){ TC_ALLOC(sb + 0, 256); TC_RELINQ(); }
    if (tid == 0){
        MBAR_INIT(sb + MB_FULL, 1);
        MBAR_INIT(sb + MB_EMPTY, 1);
    }
    if (tid < 256){
        int hb = b*TH;
        int hh = n0 + tid;
        float r = 1.f/(1.f + expf(-(g_gi[hb + hh]       + g_gh[hb + hh])));
        float z = 1.f/(1.f + expf(-(g_gi[hb + H + hh]   + g_gh[hb + H + hh])));
        float n = tanhf(g_gi[hb + 2*H + hh] + r*g_gh[hb + 2*H + hh]);
        s_state[tid] = (1.f - z)*n + z*g_prev[b*H + hh];
        s_bias[tid]  = bias[n0 + tid];
    }
    __syncthreads();
    uint32_t tmem;
    asm volatile("ld.shared.b32 %0, [%1];" : "=r"(tmem) : "r"(sb));

    int rowi[4], gi4[4];
    #pragma unroll
    for (int it = 0; it < 4; it++){
        int i = tid + it*SC_THREADS;
        rowi[it] = i >> 4; gi4[it] = i & 15;
    }

    auto prefetch_A = [&](int c, float4* pf){
        int k0 = c * 64;
        #pragma unroll
        for (int it = 0; it < 4; it++)
            pf[it] = *(const float4*)(A + (size_t)(m0+rowi[it])*KC + k0 + gi4[it]*4);
    };
    auto store_A = [&](const float4* pf){
        #pragma unroll
        for (int it = 0; it < 4; it++){
            float4 a4 = pf[it];
            uint16_t h0,h1,h2,h3,l0,l1,l2,l3;
            split_bf16(a4.x,h0,l0); split_bf16(a4.y,h1,l1);
            split_bf16(a4.z,h2,l2); split_bf16(a4.w,h3,l3);
            uint2 hv = make_uint2((uint32_t)h0 | ((uint32_t)h1<<16), (uint32_t)h2 | ((uint32_t)h3<<16));
            uint2 lv = make_uint2((uint32_t)l0 | ((uint32_t)l1<<16), (uint32_t)l2 | ((uint32_t)l3<<16));
            uint32_t off = (uint32_t)(rowi[it]*128 + gi4[it]*8);
            uint32_t sw  = off ^ ((off >> 3) & 0x70);
            *(uint2*)(smem + T_AH + sw) = hv;
            *(uint2*)(smem + T_AL + sw) = lv;
        }
    };

    const uint32_t idesc = (1u<<4) | (1u<<7) | (1u<<10) | (32u<<17) | (8u<<24);
    float4 pf[4];
    prefetch_A(0, pf);
    int phf = 0, phe = 0;

    for (int c = 0; c < NCHUNK_SC; c++){
        if (c > 0){ MBAR_WAIT(sb + MB_EMPTY, phe); phe ^= 1; }
        if (wid == 1 && elect_one()){
            int k0 = c * 64;
            MBAR_EXPECT_TX(sb + MB_FULL, 65536);
            TMA_LOAD_2D(sb + T_BH, &mapBh, k0, n0, sb + MB_FULL);
            TMA_LOAD_2D(sb + T_BL, &mapBl, k0, n0, sb + MB_FULL);
        }
        store_A(pf);
        asm volatile("fence.proxy.async.shared::cta;" ::: "memory");
        __syncthreads();
        if (c + 1 < NCHUNK_SC) prefetch_A(c + 1, pf);
        if (wid == 0 && elect_one()){
            MBAR_WAIT(sb + MB_FULL, phf); phf ^= 1;
            uint64_t dAh = MK_DESC(sb + T_AH);
            uint64_t dAl = MK_DESC(sb + T_AL);
            uint64_t dBh = MK_DESC(sb + T_BH);
            uint64_t dBl = MK_DESC(sb + T_BL);
            #pragma unroll
            for (int ks = 0; ks < 4; ks++){
                uint64_t o = (uint64_t)(ks*2);
                mma_f16_ss(tmem, dAh + o, dBh + o, idesc, (c==0 && ks==0) ? 0u : 1u);
                mma_f16_ss(tmem, dAh + o, dBl + o, idesc, 1u);
                mma_f16_ss(tmem, dAl + o, dBh + o, idesc, 1u);
            }
            TC_COMMIT(sb + MB_EMPTY);
        }
    }
    MBAR_WAIT(sb + MB_EMPTY, phe);
    TC_FENCE_AFTER();

    if (wid < 4){
        float acc = 0.f;
        #pragma unroll
        for (int c0 = 0; c0 < 256; c0 += 32){
            uint32_t r[32];
            TC_LD_X32(r, tmem + c0);
            TC_WAIT_LD();
            #pragma unroll
            for (int j = 0; j < 32; j++)
                acc += tanhf(__uint_as_float(r[j]) + s_bias[c0+j]) * s_state[c0+j];
        }
        TC_FENCE_BEFORE();
        atomicAdd(&g_scorec_raw[m0 + wid*32 + lid], acc);
    }
    __syncthreads();
    if (wid == 0) TC_DEALLOC(tmem, 256);
#endif
}

// ============ generic tc GEMM (unchanged) ============
#define HDR_W 1024
#define WSTG 49152
#define W_AH 0
#define W_AL 16384
#define W_BH 32768
#define W_BL 40960
#define WT_OFF(stg, t) (HDR_W + (uint32_t)(stg)*WSTG + (uint32_t)(t))
#define SMEM_TW (HDR_W + 2*WSTG)

__global__ void __launch_bounds__(256, 1) k_tcW(const float* __restrict__ W,
        const __nv_bfloat16* __restrict__ act_hi, const __nv_bfloat16* __restrict__ act_lo,
        float* __restrict__ out, int Nw, int K, int kpc, int ldO,
        const float* __restrict__ obias){
#if HAS_TC
    extern __shared__ char smem[];
    uint32_t sb = smem_u32(smem);
    int tid = threadIdx.x, wid = tid >> 5, lid = tid & 31;
    int m0 = blockIdx.x * 128;
    int k_base = blockIdx.y * kpc * 64;

    if (wid == 0){ TC_ALLOC(sb + 0, 64); TC_RELINQ(); }
    if (tid == 0){ MBAR_INIT(sb + 8, 1); MBAR_INIT(sb + 16, 1); }
    __syncthreads();
    uint32_t tmem;
    asm volatile("ld.shared.b32 %0, [%1];" : "=r"(tmem) : "r"(sb));

    auto load_chunk = [&](int c, int stg){
        int k0 = k_base + c * 64;
        #pragma unroll
        for (int it = 0; it < 8; it++){
            int i = tid + it*256;
            int row = i >> 4, g = i & 15;
            float4 a4 = make_float4(0.f,0.f,0.f,0.f);
            if (m0 + row < Nw) a4 = *(const float4*)(W + (size_t)(m0+row)*K + k0 + g*4);
            uint16_t h0,h1,h2,h3,l0,l1,l2,l3;
            split_bf16(a4.x,h0,l0); split_bf16(a4.y,h1,l1);
            split_bf16(a4.z,h2,l2); split_bf16(a4.w,h3,l3);
            uint2 hv = make_uint2((uint32_t)h0 | ((uint32_t)h1<<16), (uint32_t)h2 | ((uint32_t)h3<<16));
            uint2 lv = make_uint2((uint32_t)l0 | ((uint32_t)l1<<16), (uint32_t)l2 | ((uint32_t)l3<<16));
            uint32_t off = (uint32_t)(row*128 + g*8);
            uint32_t sw  = off ^ ((off >> 3) & 0x70);
            *(uint2*)(smem + WT_OFF(stg, W_AH) + sw) = hv;
            *(uint2*)(smem + WT_OFF(stg, W_AL) + sw) = lv;
        }
        #pragma unroll
        for (int it = 0; it < 2; it++){
            int i = tid + it*256;
            int row = i >> 3, g = i & 7;
            size_t base = ((size_t)row*K + k0) * 2;
            uint4 h4 = *(const uint4*)((const char*)act_hi + base + g*16);
            uint4 l4 = *(const uint4*)((const char*)act_lo + base + g*16);
            uint32_t off = (uint32_t)(row*128 + g*16);
            uint32_t sw  = off ^ ((off >> 3) & 0x70);
            *(uint4*)(smem + WT_OFF(stg, W_BH) + sw) = h4;
            *(uint4*)(smem + WT_OFF(stg, W_BL) + sw) = l4;
        }
    };

    load_chunk(0, 0);
    asm volatile("fence.proxy.async.shared::cta;" ::: "memory");
    __syncthreads();

    const uint32_t idesc = (1u<<4) | (1u<<7) | (1u<<10) | (8u<<17) | (8u<<24);   // N=64, M=128
    int ph[2] = {0, 0};

    for (int c = 0; c < kpc; c++){
        int stg = c & 1;
        if (wid == 0 && elect_one()){
            uint64_t dAh = MK_DESC(sb + WT_OFF(stg, W_AH));
            uint64_t dAl = MK_DESC(sb + WT_OFF(stg, W_AL));
            uint64_t dBh = MK_DESC(sb + WT_OFF(stg, W_BH));
            uint64_t dBl = MK_DESC(sb + WT_OFF(stg, W_BL));
            #pragma unroll
            for (int ks = 0; ks < 4; ks++){
                uint64_t o = (uint64_t)(ks*2);
                mma_f16_ss(tmem, dAh + o, dBh + o, idesc, (c==0 && ks==0) ? 0u : 1u);
                mma_f16_ss(tmem, dAh + o, dBl + o, idesc, 1u);
                mma_f16_ss(tmem, dAl + o, dBh + o, idesc, 1u);
            }
            TC_COMMIT(sb + 8 + stg*8);
        }
        if (c + 1 < kpc){
            int nst = stg ^ 1;
            if (c >= 1){ MBAR_WAIT(sb + 8 + nst*8, ph[nst]); ph[nst] ^= 1; }
            load_chunk(c + 1, nst);
            asm volatile("fence.proxy.async.shared::cta;" ::: "memory");
            __syncthreads();
        }
    }
    MBAR_WAIT(sb + 8 + ((kpc-1)&1)*8, ph[(kpc-1)&1]);
    TC_FENCE_AFTER();

    if (wid < 4){
        uint32_t r0[32], r1[32];
        TC_LD_X32(r0, tmem);
        TC_LD_X32(r1, tmem + 32);
        TC_WAIT_LD();
        TC_FENCE_BEFORE();
        int m = m0 + wid*32 + lid;
        if (m < Nw){
            if (obias){
                float bv = obias[m];
                #pragma unroll
                for (int c = 0; c < 32; c++)
                    out[(size_t)c*ldO + m] = __uint_as_float(r0[c]) + bv;
                #pragma unroll
                for (int c = 0; c < 32; c++)
                    out[(size_t)(c+32)*ldO + m] = __uint_as_float(r1[c]) + bv;
            } else {
                #pragma unroll
                for (int c = 0; c < 32; c++)
                    atomicAdd(out + (size_t)c*ldO + m, __uint_as_float(r0[c]));
                #pragma unroll
                for (int c = 0; c < 32; c++)
                    atomicAdd(out + (size_t)(c+32)*ldO + m, __uint_as_float(r1[c]));
            }
        }
    }
    __syncthreads();
    if (wid == 0) TC_DEALLOC(tmem, 64);
#endif
}

// ---------------- fused prep ----------------
__global__ void k_prep(const int* __restrict__ input_idx, const float* __restrict__ embed,
                       const float* __restrict__ weighted, const float* __restrict__ prev_state,
                       const float* __restrict__ encoded, const float* __restrict__ Ws_w,
                       const float* __restrict__ Ws_b, const float* __restrict__ bi,
                       const float* __restrict__ bh, const float* __restrict__ Wc,
                       const int* __restrict__ order, int has_order){
    int i = blockIdx.x*blockDim.x + threadIdx.x;
    int ord = has_order ? *order : 1;
    {
        int j = i % TH;
        g_gi[i] = bi[j];
        g_gh[i] = bh[j];
    }
    if (i < B*KX){
        int b = i / KX, j = i - b*KX;
        float v;
        if (j < E) v = embed[(size_t)input_idx[b]*E + j];
        else       v = ord ? weighted[b*(2*H) + (j - E)] : 0.f;
        uint16_t h, l; split_bf16(v, h, l);
        g_x_hi[i] = __ushort_as_bfloat16(h);
        g_x_lo[i] = __ushort_as_bfloat16(l);
    }
    if (i < B*H){
        float v;
        if (ord){
            v = prev_state[i];
        } else {
            int b = i >> 10, h = i & (H-1);
            const float* e = encoded + ((size_t)b*S + (S-1))*(2*H);
            const float* w = Ws_w + (size_t)h*(2*H);
            float s = Ws_b[h];
            for (int k = 0; k < 2*H; k++) s = fmaf(e[k], w[k], s);
            v = s;
        }
        g_prev[i] = v;
        uint16_t h16, l16; split_bf16(v, h16, l16);
        g_prev_hi[i] = __ushort_as_bfloat16(h16);
        g_prev_lo[i] = __ushort_as_bfloat16(l16);
    }
    if (i < B*S) g_scorec_raw[i] = 0.f;
    for (int t = i; t < (H*KC)/4; t += B*TH){
        size_t e = (size_t)t*4;
        float4 w = *(const float4*)(Wc + e);
        uint16_t h0,h1,h2,h3,l0,l1,l2,l3;
        split_bf16(w.x,h0,l0); split_bf16(w.y,h1,l1);
        split_bf16(w.z,h2,l2); split_bf16(w.w,h3,l3);
        uint2 hv = make_uint2((uint32_t)h0 | ((uint32_t)h1<<16), (uint32_t)h2 | ((uint32_t)h3<<16));
        uint2 lv = make_uint2((uint32_t)l0 | ((uint32_t)l1<<16), (uint32_t)l2 | ((uint32_t)l3<<16));
        *(uint2*)((char*)g_Wc_hi + e*2) = hv;
        *(uint2*)((char*)g_Wc_lo + e*2) = lv;
    }
}

// ---------------- GRU combine ----------------
__global__ void k_combine(float* __restrict__ out_state){
    int i = blockIdx.x*blockDim.x + threadIdx.x;
    if (i >= B*H) return;
    int b = i >> 10, h = i & (H-1);
    const float* gi = g_gi + b*TH;
    const float* gh = g_gh + b*TH;
    float r = 1.f/(1.f + expf(-(gi[h]        + gh[h])));
    float z = 1.f/(1.f + expf(-(gi[H + h]    + gh[H + h])));
    float n = tanhf(gi[2*H + h] + r*gh[2*H + h]);
    float st = (1.f - z)*n + z*g_prev[i];
    out_state[i] = st;
    uint16_t h16, l16; split_bf16(st, h16, l16);
    g_state_hi[i] = __ushort_as_bfloat16(h16);
    g_state_lo[i] = __ushort_as_bfloat16(l16);
}

// ---------------- finalize score_c ----------------
__global__ void k_scorec_fin(const int* __restrict__ encoded_idx){
    int m = blockIdx.x*blockDim.x + threadIdx.x;
    float v = tanhf(g_scorec_raw[m]);
    if (encoded_idx[m] == 0) v -= 1000.f;
    g_scorec[m] = v;
}

// ---------------- softmax stats / writeout / tail ----------------
__global__ void k_rowstats(){
    int b = blockIdx.x;
    __shared__ float red[256];
    const float* sg = g_scoreg + (size_t)b*V;
    const float* sc = g_scorec + b*S;
    float mx = -1e30f;
    for (int i = threadIdx.x; i < V; i += 256) mx = fmaxf(mx, sg[i]);
    for (int i = threadIdx.x; i < S; i += 256) mx = fmaxf(mx, sc[i]);
    red[threadIdx.x] = mx; __syncthreads();
    for (int st = 128; st; st >>= 1){
        if (threadIdx.x < st) red[threadIdx.x] = fmaxf(red[threadIdx.x], red[threadIdx.x+st]);
        __syncthreads();
    }
    mx = red[0];
    __syncthreads();
    float sm = 0.f;
    for (int i = threadIdx.x; i < V; i += 256) sm += expf(sg[i] - mx);
    for (int i = threadIdx.x; i < S; i += 256) sm += expf(sc[i] - mx);
    red[threadIdx.x] = sm; __syncthreads();
    for (int st = 128; st; st >>= 1){
        if (threadIdx.x < st) red[threadIdx.x] += red[threadIdx.x+st];
        __syncthreads();
    }
    if (threadIdx.x == 0){ g_rowmax[b] = mx; g_rowsum[b] = red[0]; }
}

__global__ void k_writeout(float* __restrict__ out){
    long long i = (long long)blockIdx.x*256 + threadIdx.x;
    if (i >= (long long)B*OUTW) return;
    int b = (int)(i / OUTW);
    int c = (int)(i - (long long)b*OUTW);
    float v;
    if (c < V) v = expf(g_scoreg[(size_t)b*V + c] - g_rowmax[b]) / g_rowsum[b];
    else       v = 1e-4f;
    out[i] = v;
}

__global__ void k_tail(float* __restrict__ out, float* __restrict__ out_w,
                       const int* __restrict__ encoded_idx, const int* __restrict__ input_idx,
                       const float* __restrict__ encoded){
    int b = blockIdx.x;
    __shared__ float pc[S];
    __shared__ float attn[S];
    __shared__ int   icnt[256];
    float mx  = g_rowmax[b];
    float inv = 1.f / g_rowsum[b];
    int target = input_idx[b];
    int c = 0;
    for (int s = threadIdx.x; s < S; s += 256){
        float p = expf(g_scorec[b*S + s] - mx) * inv;
        pc[s] = p;
        if (encoded_idx[b*S + s] == target) c++;
    }
    icnt[threadIdx.x] = c; __syncthreads();
    for (int st = 128; st; st >>= 1){
        if (threadIdx.x < st) icnt[threadIdx.x] += icnt[threadIdx.x+st];
        __syncthreads();
    }
    int ssum = icnt[0];
    float scale = (ssum > 1) ? 1.f/(float)ssum : 1.f;
    for (int s = threadIdx.x; s < S; s += 256){
        int idx = encoded_idx[b*S + s];
        atomicAdd(&out[(size_t)b*OUTW + idx], pc[s]);
        attn[s] = (idx == target) ? pc[s]*scale : 0.f;
    }
    __syncthreads();
    float acc[8] = {0.f,0.f,0.f,0.f,0.f,0.f,0.f,0.f};
    const float* eb = encoded + (size_t)b*S*(2*H);
    for (int s = 0; s < S; s++){
        float a = attn[s];
        if (a != 0.f){
            const float* er = eb + (size_t)s*(2*H);
            #pragma unroll
            for (int j = 0; j < 8; j++)
                acc[j] = fmaf(a, er[threadIdx.x + j*256], acc[j]);
        }
    }
    #pragma unroll
    for (int j = 0; j < 8; j++)
        out_w[b*(2*H) + threadIdx.x + j*256] = acc[j];
}

// ---------------- launch ----------------
typedef CUresult (*tme_fn_t)(CUtensorMap*, CUtensorMapDataType, cuuint32_t, void*,
                             const cuuint64_t*, const cuuint64_t*, const cuuint32_t*,
                             const cuuint32_t*, CUtensorMapInterleave, CUtensorMapSwizzle,
                             CUtensorMapL2promotion, CUtensorMapFloatOOBfill);

extern "C" void kernel_launch(void* const* d_in, const int* in_sizes, int n_in,
                              void* d_out, int out_size){
    const int*   input_idx   = (const int*)  d_in[0];
    const float* encoded     = (const float*)d_in[1];
    const int*   encoded_idx = (const int*)  d_in[2];
    const float* prev_state  = (const float*)d_in[3];
    const float* weighted    = (const float*)d_in[4];
    int off = 0;
    const int* order = nullptr;
    if (n_in >= 17 && in_sizes[5] == 1){ order = (const int*)d_in[5]; off = 1; }
    const float* embed  = (const float*)d_in[5+off];
    const float* gru_wi = (const float*)d_in[6+off];
    const float* gru_wh = (const float*)d_in[7+off];
    const float* gru_bi = (const float*)d_in[8+off];
    const float* gru_bh = (const float*)d_in[9+off];
    const float* Ws_w   = (const float*)d_in[10+off];
    const float* Ws_b   = (const float*)d_in[11+off];
    const float* Wg_w   = (const float*)d_in[12+off];
    const float* Wg_b   = (const float*)d_in[13+off];
    const float* Wc_w   = (const float*)d_in[14+off];
    const float* Wc_b   = (const float*)d_in[15+off];
    int has_order = (order != nullptr);
    if (!order) order = input_idx;

    float* out       = (float*)d_out;
    float* out_state = out + (size_t)B*OUTW;
    float* out_w     = out_state + (size_t)B*H;

    static float *p_gi = nullptr, *p_gh, *p_scoreg;
    static __nv_bfloat16 *p_Bh, *p_Bl, *p_xh, *p_xl, *p_ph, *p_pl, *p_sh, *p_sl;
    static CUtensorMap mapBh, mapBl;
    static cudaStream_t s2;
    static cudaEvent_t evFork, evJoin;
    if (!p_gi){
        cudaGetSymbolAddress((void**)&p_gi,     g_gi);
        cudaGetSymbolAddress((void**)&p_gh,     g_gh);
        cudaGetSymbolAddress((void**)&p_scoreg, g_scoreg);
        cudaGetSymbolAddress((void**)&p_Bh,     g_Wc_hi);
        cudaGetSymbolAddress((void**)&p_Bl,     g_Wc_lo);
        cudaGetSymbolAddress((void**)&p_xh,     g_x_hi);
        cudaGetSymbolAddress((void**)&p_xl,     g_x_lo);
        cudaGetSymbolAddress((void**)&p_ph,     g_prev_hi);
        cudaGetSymbolAddress((void**)&p_pl,     g_prev_lo);
        cudaGetSymbolAddress((void**)&p_sh,     g_state_hi);
        cudaGetSymbolAddress((void**)&p_sl,     g_state_lo);
        cudaFuncSetAttribute(k_tc_sc, cudaFuncAttributeMaxDynamicSharedMemorySize, SMEM_TC);
        cudaFuncSetAttribute(k_tcW,   cudaFuncAttributeMaxDynamicSharedMemorySize, SMEM_TW);
        cudaStreamCreateWithFlags(&s2, cudaStreamNonBlocking);
        cudaEventCreateWithFlags(&evFork, cudaEventDisableTiming);
        cudaEventCreateWithFlags(&evJoin, cudaEventDisableTiming);

        void* fn = nullptr;
        cudaDriverEntryPointQueryResult qr;
        cudaGetDriverEntryPointByVersion("cuTensorMapEncodeTiled", &fn, 12000,
                                         cudaEnableDefault, &qr);
        tme_fn_t enc = (tme_fn_t)fn;
        cuuint64_t dims[2]    = {(cuuint64_t)KC, (cuuint64_t)H};
        cuuint64_t strides[1] = {(cuuint64_t)KC * 2};
        cuuint32_t box[2]     = {64, 256};
        cuuint32_t es[2]      = {1, 1};
        enc(&mapBh, CU_TENSOR_MAP_DATA_TYPE_BFLOAT16, 2, p_Bh, dims, strides, box, es,
            CU_TENSOR_MAP_INTERLEAVE_NONE, CU_TENSOR_MAP_SWIZZLE_128B,
            CU_TENSOR_MAP_L2_PROMOTION_L2_128B, CU_TENSOR_MAP_FLOAT_OOB_FILL_NONE);
        enc(&mapBl, CU_TENSOR_MAP_DATA_TYPE_BFLOAT16, 2, p_Bl, dims, strides, box, es,
            CU_TENSOR_MAP_INTERLEAVE_NONE, CU_TENSOR_MAP_SWIZZLE_128B,
            CU_TENSOR_MAP_L2_PROMOTION_L2_128B, CU_TENSOR_MAP_FLOAT_OOB_FILL_NONE);
    }

    // launch 0: fused prep (incl Wc conversion)
    k_prep<<<(B*TH)/256, 256>>>(input_idx, embed, weighted, prev_state, encoded,
                                Ws_w, Ws_b, gru_bi, gru_bh, Wc_w, order, has_order);
    // 1, 2: GRU gate GEMMs
    k_tcW<<<dim3(TH/128, 5), 256, SMEM_TW>>>(gru_wi, p_xh, p_xl, p_gi, TH, KX, 8, TH, nullptr);
    k_tcW<<<dim3(TH/128, 4), 256, SMEM_TW>>>(gru_wh, p_ph, p_pl, p_gh, TH, H,  4, TH, nullptr);

    // fork: side stream does combine + Wg GEMM while tc_sc runs on the main stream
    cudaEventRecord(evFork, 0);
    cudaStreamWaitEvent(s2, evFork, 0);
    k_combine<<<(B*H)/256, 256, 0, s2>>>(out_state);
    k_tcW<<<dim3((V+127)/128, 1), 256, SMEM_TW, s2>>>(Wg_w, p_sh, p_sl, p_scoreg, V, H, H/64, V, Wg_b);
    cudaEventRecord(evJoin, s2);

    // main stream: big fused GEMM (single-stage, 2 CTA/SM)
    k_tc_sc<<<dim3(H/256, MS/128), SC_THREADS, SMEM_TC>>>(encoded, mapBh, mapBl, Wc_b);

    // join
    cudaStreamWaitEvent(0, evJoin, 0);

    k_scorec_fin<<<MS/256, 256>>>(encoded_idx);
    k_rowstats<<<B, 256>>>();
    k_writeout<<<((long long)B*OUTW + 255)/256, 256>>>(out);
    k_tail    <<<B, 256>>>(out, out_w, encoded_idx, input_idx, encoded);
}